// round 9
// baseline (speedup 1.0000x reference)
#include <cuda_runtime.h>

// ---------------------------------------------------------------------------
// AI4Urban CFD step on 64x256x256 grid. All scratch in one __device__ heap.
// ---------------------------------------------------------------------------

#define TPB 256

constexpr int NZ_ = 64, NY_ = 256, NX_ = 256;
constexpr int NI_ = NZ_ * NY_ * NX_;            // 4194304 interior cells
constexpr int PZ_ = NZ_ + 2, PY_ = NY_ + 2, PX_ = NX_ + 2;
constexpr int SY_ = PX_;                         // 258
constexpr int SZ_ = PY_ * PX_;                   // 66564
constexpr int PT_ = PZ_ * SZ_;                   // 4393224 padded cells

constexpr float RE_ = 0.15f;
constexpr float DX_ = 1.0f;
constexpr float UB_ = -1.0f;

// multigrid level sizes (levels 1..5; level 0 = NI_)
constexpr int L1_ = 32 * 128 * 128;
constexpr int L2_ = 16 * 64 * 64;
constexpr int L3_ = 8 * 32 * 32;
constexpr int L4_ = 4 * 16 * 16;
constexpr int L5_ = 2 * 8 * 8;

// ----- heap layout ---------------------------------------------------------
constexpr long long O_UU  = 0;
constexpr long long O_VV  = O_UU  + PT_;
constexpr long long O_WW  = O_VV  + PT_;
constexpr long long O_PPb = O_WW  + PT_;
constexpr long long O_KUU = O_PPb + PT_;
constexpr long long O_KVV = O_KUU + PT_;
constexpr long long O_KWW = O_KVV + PT_;

constexpr long long O_U    = O_KWW + PT_;
constexpr long long O_V    = O_U    + NI_;
constexpr long long O_W    = O_V    + NI_;
constexpr long long O_BU   = O_W    + NI_;
constexpr long long O_BV   = O_BU   + NI_;
constexpr long long O_BW   = O_BV   + NI_;
constexpr long long O_GPX  = O_BW   + NI_;
constexpr long long O_GPY  = O_GPX  + NI_;
constexpr long long O_GPZ  = O_GPY  + NI_;
constexpr long long O_ADXU = O_GPZ  + NI_;
constexpr long long O_ADYU = O_ADXU + NI_;
constexpr long long O_ADZU = O_ADYU + NI_;
constexpr long long O_AD2U = O_ADZU + NI_;
constexpr long long O_ADXV = O_AD2U + NI_;
constexpr long long O_ADYV = O_ADXV + NI_;
constexpr long long O_ADZV = O_ADYV + NI_;
constexpr long long O_AD2V = O_ADZV + NI_;
constexpr long long O_ADXW = O_AD2V + NI_;
constexpr long long O_ADYW = O_ADXW + NI_;
constexpr long long O_ADZW = O_ADYW + NI_;
constexpr long long O_AD2W = O_ADZW + NI_;
constexpr long long O_KX   = O_AD2W + NI_;
constexpr long long O_KY   = O_KX   + NI_;
constexpr long long O_KZ   = O_KY   + NI_;
constexpr long long O_P    = O_KZ   + NI_;
constexpr long long O_RHS  = O_P    + NI_;
constexpr long long O_SCR  = O_RHS  + NI_;
constexpr long long O_R0   = O_SCR  + NI_;
constexpr long long O_MW0  = O_R0   + NI_;
constexpr long long O_R1   = O_MW0  + NI_;
constexpr long long O_R2   = O_R1   + L1_;
constexpr long long O_R3   = O_R2   + L2_;
constexpr long long O_R4   = O_R3   + L3_;
constexpr long long O_R5   = O_R4   + L4_;
constexpr long long O_MW1  = O_R5   + L5_;
constexpr long long O_MW2  = O_MW1  + L1_;
constexpr long long O_MW3  = O_MW2  + L2_;
constexpr long long O_MW4  = O_MW3  + L3_;
constexpr long long O_MW5  = O_MW4  + L4_;
constexpr long long HEAP_N = O_MW5  + L5_;

__device__ float g_heap[HEAP_N];
__device__ float g_dt_fb = 0.5f;   // fallback dt if not passed as input

// robust dt loader (handles dt stored as f32 or f64)
__device__ __forceinline__ float get_dt(const float* p) {
    float f = *p;
    if (f > 1e-20f && f < 1e20f) return f;
    return (float)(*(const double*)p);
}

__device__ __forceinline__ float conv27(const float* __restrict__ s, int p,
                                        const float* __restrict__ wt) {
    float acc = 0.f;
#pragma unroll
    for (int dz = 0; dz < 3; ++dz)
#pragma unroll
        for (int dy = 0; dy < 3; ++dy)
#pragma unroll
            for (int dx = 0; dx < 3; ++dx)
                acc = fmaf(__ldg(&wt[dz * 9 + dy * 3 + dx]),
                           s[p + (dz - 1) * SZ_ + (dy - 1) * SY_ + (dx - 1)], acc);
    return acc;
}

// ----- elementwise: solid body on inputs ------------------------------------
__global__ void k_solid(const float* __restrict__ su, const float* __restrict__ sv,
                        const float* __restrict__ sw, const float* __restrict__ sg,
                        const float* __restrict__ dtp) {
    int i = blockIdx.x * TPB + threadIdx.x;
    if (i >= NI_) return;
    float dt = get_dt(dtp);
    float s = 1.f / (1.f + dt * sg[i]);
    g_heap[O_U + i] = su[i] * s;
    g_heap[O_V + i] = sv[i] * s;
    g_heap[O_W + i] = sw[i] * s;
}

// ----- boundary-condition padded builds -------------------------------------
__global__ void k_bc_u(const float* __restrict__ s, float* __restrict__ d) {
    int idx = blockIdx.x * TPB + threadIdx.x;
    if (idx >= PT_) return;
    int z = idx / SZ_; int r = idx - z * SZ_; int y = r / SY_; int x = r - y * SY_;
    float val;
    if (z == 0) {
        val = 0.f;
    } else {
        int zz = (z == PZ_ - 1) ? (PZ_ - 2) : z;
        int yy = (y == 0) ? 1 : ((y == PY_ - 1) ? (PY_ - 2) : y);
        if (x == 0 || x == PX_ - 1) val = UB_;
        else val = s[((zz - 1) * NY_ + (yy - 1)) * NX_ + (x - 1)];
    }
    d[idx] = val;
}

__global__ void k_bc_v(const float* __restrict__ s, float* __restrict__ d) {
    int idx = blockIdx.x * TPB + threadIdx.x;
    if (idx >= PT_) return;
    int z = idx / SZ_; int r = idx - z * SZ_; int y = r / SY_; int x = r - y * SY_;
    float val = 0.f;
    if (z != 0) {
        int zz = (z == PZ_ - 1) ? (PZ_ - 2) : z;
        if (!(y == 0 || y == PY_ - 1 || x == 0 || x == PX_ - 1))
            val = s[((zz - 1) * NY_ + (y - 1)) * NX_ + (x - 1)];
    }
    d[idx] = val;
}

__global__ void k_bc_w(const float* __restrict__ s, float* __restrict__ d) {
    int idx = blockIdx.x * TPB + threadIdx.x;
    if (idx >= PT_) return;
    int z = idx / SZ_; int r = idx - z * SZ_; int y = r / SY_; int x = r - y * SY_;
    float val = 0.f;
    if (!(z == 0 || z == PZ_ - 1 || y == 0 || y == PY_ - 1 || x == 0 || x == PX_ - 1))
        val = s[((z - 1) * NY_ + (y - 1)) * NX_ + (x - 1)];
    d[idx] = val;
}

__global__ void k_bc_p(const float* __restrict__ s, float* __restrict__ d) {
    int idx = blockIdx.x * TPB + threadIdx.x;
    if (idx >= PT_) return;
    int z = idx / SZ_; int r = idx - z * SZ_; int y = r / SY_; int x = r - y * SY_;
    float val;
    if (x == PX_ - 1) {
        val = 0.f;
    } else {
        int zz = (z == 0) ? 1 : ((z == PZ_ - 1) ? (PZ_ - 2) : z);
        int yy = (y == 0) ? 1 : ((y == PY_ - 1) ? (PY_ - 2) : y);
        int xx = (x == 0) ? 1 : x;
        val = s[((zz - 1) * NY_ + (yy - 1)) * NX_ + (xx - 1)];
    }
    d[idx] = val;
}

// ----- fused 4-stencil (w1,w2,w3,w4) on one padded field --------------------
__global__ void k_stencil4(const float* __restrict__ src,
                           const float* __restrict__ wa, const float* __restrict__ wb,
                           const float* __restrict__ wc, const float* __restrict__ wd,
                           float* __restrict__ oa, float* __restrict__ ob,
                           float* __restrict__ oc, float* __restrict__ od) {
    int i = blockIdx.x * TPB + threadIdx.x;
    if (i >= NI_) return;
    int z = i / (NY_ * NX_); int r = i - z * NY_ * NX_; int y = r / NX_; int x = r - y * NX_;
    int p = (z + 1) * SZ_ + (y + 1) * SY_ + (x + 1);
    float n[27];
#pragma unroll
    for (int dz = 0; dz < 3; ++dz)
#pragma unroll
        for (int dy = 0; dy < 3; ++dy)
#pragma unroll
            for (int dx = 0; dx < 3; ++dx)
                n[dz * 9 + dy * 3 + dx] =
                    src[p + (dz - 1) * SZ_ + (dy - 1) * SY_ + (dx - 1)];
    float a = 0.f, b = 0.f, c = 0.f, d = 0.f;
#pragma unroll
    for (int k = 0; k < 27; ++k) {
        float nv = n[k];
        a = fmaf(__ldg(&wa[k]), nv, a);
        b = fmaf(__ldg(&wb[k]), nv, b);
        c = fmaf(__ldg(&wc[k]), nv, c);
        d = fmaf(__ldg(&wd[k]), nv, d);
    }
    oa[i] = a; ob[i] = b; oc[i] = c; od[i] = d;
}

// ----- k coefficients (all 3 fields) into padded buffers (halo = 0) ---------
__global__ void k_kcoef(const float* __restrict__ vu, const float* __restrict__ vv,
                        const float* __restrict__ vw, const float* __restrict__ k1,
                        const float* __restrict__ sg, const float* __restrict__ dtp) {
    int idx = blockIdx.x * TPB + threadIdx.x;
    if (idx >= PT_) return;
    int z = idx / SZ_; int r = idx - z * SZ_; int y = r / SY_; int x = r - y * SY_;
    if (z == 0 || z == PZ_ - 1 || y == 0 || y == PY_ - 1 || x == 0 || x == PX_ - 1) {
        g_heap[O_KUU + idx] = 0.f;
        g_heap[O_KVV + idx] = 0.f;
        g_heap[O_KWW + idx] = 0.f;
        return;
    }
    int i = ((z - 1) * NY_ + (y - 1)) * NX_ + (x - 1);
    float dt = get_dt(dtp);
    float inv = 1.f / (1.f + dt * sg[i]);
    float speed = (fabsf(vu[i]) + fabsf(vv[i]) + fabsf(vw[i])) * DX_;
    const float c = 1.f / (DX_ * DX_ * DX_);
    float lim = k1[i];
    {
        float num = 0.1f * DX_ * fabsf((1.f / 3.f) * c * speed * g_heap[O_AD2U + i]);
        float den = 0.001f + (fabsf(g_heap[O_ADXU + i]) * c + fabsf(g_heap[O_ADYU + i]) * c +
                              fabsf(g_heap[O_ADZU + i]) * c) * (1.f / 3.f);
        g_heap[O_KUU + idx] = fminf(num / den, lim) * inv;
    }
    {
        float num = 0.1f * DX_ * fabsf((1.f / 3.f) * c * speed * g_heap[O_AD2V + i]);
        float den = 0.001f + (fabsf(g_heap[O_ADXV + i]) * c + fabsf(g_heap[O_ADYV + i]) * c +
                              fabsf(g_heap[O_ADZV + i]) * c) * (1.f / 3.f);
        g_heap[O_KVV + idx] = fminf(num / den, lim) * inv;
    }
    {
        float num = 0.1f * DX_ * fabsf((1.f / 3.f) * c * speed * g_heap[O_AD2W + i]);
        float den = 0.001f + (fabsf(g_heap[O_ADXW + i]) * c + fabsf(g_heap[O_ADYW + i]) * c +
                              fabsf(g_heap[O_ADZW + i]) * c) * (1.f / 3.f);
        g_heap[O_KWW + idx] = fminf(num / den, lim) * inv;
    }
}

// ----- PG flux: 0.5*(k*AD2 + conv(f*k,w1) - f*conv(k,w1)) --------------------
__global__ void k_pgflux(const float* __restrict__ fpad, const float* __restrict__ kpad,
                         const float* __restrict__ ad2, const float* __restrict__ vel,
                         const float* __restrict__ w1p, float* __restrict__ out) {
    int i = blockIdx.x * TPB + threadIdx.x;
    if (i >= NI_) return;
    int z = i / (NY_ * NX_); int r = i - z * NY_ * NX_; int y = r / NX_; int x = r - y * NX_;
    int p = (z + 1) * SZ_ + (y + 1) * SY_ + (x + 1);
    float acc1 = 0.f, acc2 = 0.f;
#pragma unroll
    for (int dz = 0; dz < 3; ++dz)
#pragma unroll
        for (int dy = 0; dy < 3; ++dy)
#pragma unroll
            for (int dx = 0; dx < 3; ++dx) {
                int off = (dz - 1) * SZ_ + (dy - 1) * SY_ + (dx - 1);
                float wgt = __ldg(&w1p[dz * 9 + dy * 3 + dx]);
                float kv = kpad[p + off];
                acc1 = fmaf(wgt, fpad[p + off] * kv, acc1);
                acc2 = fmaf(wgt, kv, acc2);
            }
    float kc = kpad[p];
    out[i] = 0.5f * (kc * ad2[i] + acc1 - vel[i] * acc2);
}

// ----- predictor half step ---------------------------------------------------
__global__ void k_predictor(const float* __restrict__ sg, const float* __restrict__ dtp) {
    int i = blockIdx.x * TPB + threadIdx.x;
    if (i >= NI_) return;
    float dt = get_dt(dtp);
    float s = 1.f / (1.f + dt * sg[i]);
    float U = g_heap[O_U + i], V = g_heap[O_V + i], W = g_heap[O_W + i];
    g_heap[O_BU + i] = (U + 0.5f * dt * (RE_ * g_heap[O_AD2U + i] - U * g_heap[O_ADXU + i]
                          - V * g_heap[O_ADYU + i] - W * g_heap[O_ADZU + i])
                          + 0.5f * dt * g_heap[O_KX + i] - dt * g_heap[O_GPX + i]) * s;
    g_heap[O_BV + i] = (V + 0.5f * dt * (RE_ * g_heap[O_AD2V + i] - U * g_heap[O_ADXV + i]
                          - V * g_heap[O_ADYV + i] - W * g_heap[O_ADZV + i])
                          + 0.5f * dt * g_heap[O_KY + i] - dt * g_heap[O_GPY + i]) * s;
    g_heap[O_BW + i] = (W + 0.5f * dt * (RE_ * g_heap[O_AD2W + i] - U * g_heap[O_ADXW + i]
                          - V * g_heap[O_ADYW + i] - W * g_heap[O_ADZW + i])
                          + 0.5f * dt * g_heap[O_KZ + i] - dt * g_heap[O_GPZ + i]) * s;
}

// ----- corrector full step ----------------------------------------------------
__global__ void k_corrector(const float* __restrict__ sg, const float* __restrict__ dtp) {
    int i = blockIdx.x * TPB + threadIdx.x;
    if (i >= NI_) return;
    float dt = get_dt(dtp);
    float s = 1.f / (1.f + dt * sg[i]);
    float U = g_heap[O_U + i], V = g_heap[O_V + i], W = g_heap[O_W + i];
    float BU = g_heap[O_BU + i], BV = g_heap[O_BV + i], BW = g_heap[O_BW + i];
    g_heap[O_U + i] = (U + dt * (RE_ * g_heap[O_AD2U + i] - BU * g_heap[O_ADXU + i]
                         - BV * g_heap[O_ADYU + i] - BW * g_heap[O_ADZU + i]
                         + g_heap[O_KX + i]) - dt * g_heap[O_GPX + i]) * s;
    g_heap[O_V + i] = (V + dt * (RE_ * g_heap[O_AD2V + i] - BU * g_heap[O_ADXV + i]
                         - BV * g_heap[O_ADYV + i] - BW * g_heap[O_ADZV + i]
                         + g_heap[O_KY + i]) - dt * g_heap[O_GPY + i]) * s;
    g_heap[O_W + i] = (W + dt * (RE_ * g_heap[O_AD2W + i] - BU * g_heap[O_ADXW + i]
                         - BV * g_heap[O_ADYW + i] - BW * g_heap[O_ADZW + i]
                         + g_heap[O_KZ + i]) - dt * g_heap[O_GPZ + i]) * s;
}

// ----- multigrid RHS: b = -div(u)/dt ------------------------------------------
__global__ void k_divrhs(const float* __restrict__ w2, const float* __restrict__ w3,
                         const float* __restrict__ w4, const float* __restrict__ dtp) {
    int i = blockIdx.x * TPB + threadIdx.x;
    if (i >= NI_) return;
    int z = i / (NY_ * NX_); int r = i - z * NY_ * NX_; int y = r / NX_; int x = r - y * NX_;
    int p = (z + 1) * SZ_ + (y + 1) * SY_ + (x + 1);
    float a = conv27(g_heap + O_UU, p, w2);
    float b = conv27(g_heap + O_VV, p, w3);
    float c = conv27(g_heap + O_WW, p, w4);
    g_heap[O_RHS + i] = -(a + b + c) / get_dt(dtp);
}

// ----- residual level 0 ---------------------------------------------------------
__global__ void k_resid0(const float* __restrict__ wA) {
    int i = blockIdx.x * TPB + threadIdx.x;
    if (i >= NI_) return;
    int z = i / (NY_ * NX_); int r = i - z * NY_ * NX_; int y = r / NX_; int x = r - y * NX_;
    int p = (z + 1) * SZ_ + (y + 1) * SY_ + (x + 1);
    g_heap[O_R0 + i] = conv27(g_heap + O_PPb, p, wA) - g_heap[O_RHS + i];
}

// ----- restriction (2x2x2 weighted avg, stride 2) -------------------------------
__global__ void k_restrict(const float* __restrict__ fine, float* __restrict__ coarse,
                           int cz, int cy, int cx, const float* __restrict__ wr) {
    int n = cz * cy * cx;
    int i = blockIdx.x * TPB + threadIdx.x;
    if (i >= n) return;
    int z = i / (cy * cx); int r = i - z * cy * cx; int y = r / cx; int x = r - y * cx;
    int fsy = 2 * cx;
    int fsz = fsy * 2 * cy;
    int base = (2 * z) * fsz + (2 * y) * fsy + 2 * x;
    float acc = 0.f;
#pragma unroll
    for (int jz = 0; jz < 2; ++jz)
#pragma unroll
        for (int jy = 0; jy < 2; ++jy)
#pragma unroll
            for (int jx = 0; jx < 2; ++jx)
                acc = fmaf(__ldg(&wr[jz * 4 + jy * 2 + jx]),
                           fine[base + jz * fsz + jy * fsy + jx], acc);
    coarse[i] = acc;
}

// ----- fused Jacobi smooth + prolongation ---------------------------------------
__global__ void k_smooth_prol(const float* __restrict__ wc, const float* __restrict__ rr,
                              float* __restrict__ wn, int dzs, int dys, int dxs,
                              const float* __restrict__ wA) {
    int n = dzs * dys * dxs;
    int i = blockIdx.x * TPB + threadIdx.x;
    if (i >= n) return;
    int z = i / (dys * dxs); int r = i - z * dys * dxs; int y = r / dxs; int x = r - y * dxs;
    float diag = __ldg(&wA[13]);
    float acc = 0.f;
#pragma unroll
    for (int dz = -1; dz <= 1; ++dz)
#pragma unroll
        for (int dy = -1; dy <= 1; ++dy)
#pragma unroll
            for (int dx = -1; dx <= 1; ++dx) {
                int zz = z + dz, yy = y + dy, xx = x + dx;
                float v = 0.f;
                if (zz >= 0 && zz < dzs && yy >= 0 && yy < dys && xx >= 0 && xx < dxs)
                    v = wc[(zz * dys + yy) * dxs + xx];
                acc = fmaf(__ldg(&wA[(dz + 1) * 9 + (dy + 1) * 3 + (dx + 1)]), v, acc);
            }
    float val = wc[i] - acc / diag + rr[i] / diag;
    int fsy = 2 * dxs;
    int fsz = fsy * 2 * dys;
    int fb = (2 * z) * fsz + (2 * y) * fsy + 2 * x;
    wn[fb] = val;             wn[fb + 1] = val;
    wn[fb + fsy] = val;       wn[fb + fsy + 1] = val;
    wn[fb + fsz] = val;       wn[fb + fsz + 1] = val;
    wn[fb + fsz + fsy] = val; wn[fb + fsz + fsy + 1] = val;
}

// ----- p -= w0 -------------------------------------------------------------------
__global__ void k_psub() {
    int i = blockIdx.x * TPB + threadIdx.x;
    if (i >= NI_) return;
    g_heap[O_P + i] -= g_heap[O_MW0 + i];
}

// ----- p = p - conv(pp,wA)/diag + rhs/diag ----------------------------------------
__global__ void k_pupdate(const float* __restrict__ wA) {
    int i = blockIdx.x * TPB + threadIdx.x;
    if (i >= NI_) return;
    int z = i / (NY_ * NX_); int r = i - z * NY_ * NX_; int y = r / NX_; int x = r - y * NX_;
    int p = (z + 1) * SZ_ + (y + 1) * SY_ + (x + 1);
    float diag = __ldg(&wA[13]);
    float cv = conv27(g_heap + O_PPb, p, wA);
    g_heap[O_P + i] = g_heap[O_P + i] - cv / diag + g_heap[O_RHS + i] / diag;
}

// ----- final: u -= grad(p)*dt, solid_body, write outputs --------------------------
__global__ void k_final(const float* __restrict__ w2, const float* __restrict__ w3,
                        const float* __restrict__ w4, const float* __restrict__ sg,
                        const float* __restrict__ dtp, float* __restrict__ out) {
    int i = blockIdx.x * TPB + threadIdx.x;
    if (i >= NI_) return;
    int z = i / (NY_ * NX_); int r = i - z * NY_ * NX_; int y = r / NX_; int x = r - y * NX_;
    int p = (z + 1) * SZ_ + (y + 1) * SY_ + (x + 1);
    float n[27];
#pragma unroll
    for (int dz = 0; dz < 3; ++dz)
#pragma unroll
        for (int dy = 0; dy < 3; ++dy)
#pragma unroll
            for (int dx = 0; dx < 3; ++dx)
                n[dz * 9 + dy * 3 + dx] =
                    g_heap[O_PPb + p + (dz - 1) * SZ_ + (dy - 1) * SY_ + (dx - 1)];
    float gx = 0.f, gy = 0.f, gz = 0.f;
#pragma unroll
    for (int k = 0; k < 27; ++k) {
        float nv = n[k];
        gx = fmaf(__ldg(&w2[k]), nv, gx);
        gy = fmaf(__ldg(&w3[k]), nv, gy);
        gz = fmaf(__ldg(&w4[k]), nv, gz);
    }
    float dt = get_dt(dtp);
    float s = 1.f / (1.f + dt * sg[i]);
    out[i] = (g_heap[O_U + i] - dt * gx) * s;
    out[(long long)NI_ + i] = (g_heap[O_V + i] - dt * gy) * s;
    out[2LL * NI_ + i] = (g_heap[O_W + i] - dt * gz) * s;
    out[3LL * NI_ + i] = g_heap[O_P + i];
    out[4LL * NI_ + i] = g_heap[O_MW0 + i];
}

// ---------------------------------------------------------------------------
extern "C" void kernel_launch(void* const* d_in, const int* in_sizes, int n_in,
                              void* d_out, int out_size) {
    const float* in_u = (const float*)d_in[0];
    const float* in_v = (const float*)d_in[2];
    const float* in_w = (const float*)d_in[4];
    const float* in_p = (const float*)d_in[6];
    const float* k1   = (const float*)d_in[11];
    const float* sg   = (const float*)d_in[15];
    const float* wA   = (const float*)d_in[16];
    const float* w1   = (const float*)d_in[17];
    const float* w2   = (const float*)d_in[18];
    const float* w3   = (const float*)d_in[19];
    const float* w4   = (const float*)d_in[20];
    const float* wres = (const float*)d_in[21];

    float* H = nullptr;
    cudaGetSymbolAddress((void**)&H, g_heap);

    const float* dtp;
    if (n_in > 22) {
        dtp = (const float*)d_in[22];
    } else {
        float* fb = nullptr;
        cudaGetSymbolAddress((void**)&fb, g_dt_fb);
        dtp = fb;
    }

    float* out = (float*)d_out;
    const int GI = (NI_ + TPB - 1) / TPB;
    const int GP = (PT_ + TPB - 1) / TPB;

    // stage A: solid body, BCs, stencils, PG, predictor
    k_solid<<<GI, TPB>>>(in_u, in_v, in_w, sg, dtp);
    k_bc_u<<<GP, TPB>>>(H + O_U, H + O_UU);
    k_bc_v<<<GP, TPB>>>(H + O_V, H + O_VV);
    k_bc_w<<<GP, TPB>>>(H + O_W, H + O_WW);
    k_bc_p<<<GP, TPB>>>(in_p, H + O_PPb);
    k_stencil4<<<GI, TPB>>>(H + O_UU, w1, w2, w3, w4, H + O_AD2U, H + O_ADXU, H + O_ADYU, H + O_ADZU);
    k_stencil4<<<GI, TPB>>>(H + O_VV, w1, w2, w3, w4, H + O_AD2V, H + O_ADXV, H + O_ADYV, H + O_ADZV);
    k_stencil4<<<GI, TPB>>>(H + O_WW, w1, w2, w3, w4, H + O_AD2W, H + O_ADXW, H + O_ADYW, H + O_ADZW);
    k_stencil4<<<GI, TPB>>>(H + O_PPb, w1, w2, w3, w4, H + O_SCR, H + O_GPX, H + O_GPY, H + O_GPZ);
    k_kcoef<<<GP, TPB>>>(H + O_U, H + O_V, H + O_W, k1, sg, dtp);
    k_pgflux<<<GI, TPB>>>(H + O_UU, H + O_KUU, H + O_AD2U, H + O_U, w1, H + O_KX);
    k_pgflux<<<GI, TPB>>>(H + O_VV, H + O_KVV, H + O_AD2V, H + O_V, w1, H + O_KY);
    k_pgflux<<<GI, TPB>>>(H + O_WW, H + O_KWW, H + O_AD2W, H + O_W, w1, H + O_KZ);
    k_predictor<<<GI, TPB>>>(sg, dtp);

    // stage B: BCs on predictor, stencils, PG, corrector
    k_bc_u<<<GP, TPB>>>(H + O_BU, H + O_UU);
    k_bc_v<<<GP, TPB>>>(H + O_BV, H + O_VV);
    k_bc_w<<<GP, TPB>>>(H + O_BW, H + O_WW);
    k_stencil4<<<GI, TPB>>>(H + O_UU, w1, w2, w3, w4, H + O_AD2U, H + O_ADXU, H + O_ADYU, H + O_ADZU);
    k_stencil4<<<GI, TPB>>>(H + O_VV, w1, w2, w3, w4, H + O_AD2V, H + O_ADXV, H + O_ADYV, H + O_ADZV);
    k_stencil4<<<GI, TPB>>>(H + O_WW, w1, w2, w3, w4, H + O_AD2W, H + O_ADXW, H + O_ADYW, H + O_ADZW);
    k_kcoef<<<GP, TPB>>>(H + O_BU, H + O_BV, H + O_BW, k1, sg, dtp);
    k_pgflux<<<GI, TPB>>>(H + O_UU, H + O_KUU, H + O_AD2U, H + O_BU, w1, H + O_KX);
    k_pgflux<<<GI, TPB>>>(H + O_VV, H + O_KVV, H + O_AD2V, H + O_BV, w1, H + O_KY);
    k_pgflux<<<GI, TPB>>>(H + O_WW, H + O_KWW, H + O_AD2W, H + O_BW, w1, H + O_KZ);
    k_corrector<<<GI, TPB>>>(sg, dtp);

    // final BCs + multigrid pressure solve
    k_bc_u<<<GP, TPB>>>(H + O_U, H + O_UU);
    k_bc_v<<<GP, TPB>>>(H + O_V, H + O_VV);
    k_bc_w<<<GP, TPB>>>(H + O_W, H + O_WW);
    k_divrhs<<<GI, TPB>>>(w2, w3, w4, dtp);
    cudaMemcpyAsync(H + O_P, in_p, (size_t)NI_ * sizeof(float), cudaMemcpyDeviceToDevice, 0);

    for (int it = 0; it < 2; ++it) {   // ITERATION = 2 (fixed by problem)
        k_bc_p<<<GP, TPB>>>(H + O_P, H + O_PPb);
        k_resid0<<<GI, TPB>>>(wA);
        k_restrict<<<(L1_ + TPB - 1) / TPB, TPB>>>(H + O_R0, H + O_R1, 32, 128, 128, wres);
        k_restrict<<<(L2_ + TPB - 1) / TPB, TPB>>>(H + O_R1, H + O_R2, 16, 64, 64, wres);
        k_restrict<<<(L3_ + TPB - 1) / TPB, TPB>>>(H + O_R2, H + O_R3, 8, 32, 32, wres);
        k_restrict<<<(L4_ + TPB - 1) / TPB, TPB>>>(H + O_R3, H + O_R4, 4, 16, 16, wres);
        k_restrict<<<1, TPB>>>(H + O_R4, H + O_R5, 2, 8, 8, wres);
        cudaMemsetAsync(H + O_MW5, 0, L5_ * sizeof(float), 0);
        k_smooth_prol<<<1, TPB>>>(H + O_MW5, H + O_R5, H + O_MW4, 2, 8, 8, wA);
        k_smooth_prol<<<(L4_ + TPB - 1) / TPB, TPB>>>(H + O_MW4, H + O_R4, H + O_MW3, 4, 16, 16, wA);
        k_smooth_prol<<<(L3_ + TPB - 1) / TPB, TPB>>>(H + O_MW3, H + O_R3, H + O_MW2, 8, 32, 32, wA);
        k_smooth_prol<<<(L2_ + TPB - 1) / TPB, TPB>>>(H + O_MW2, H + O_R2, H + O_MW1, 16, 64, 64, wA);
        k_smooth_prol<<<(L1_ + TPB - 1) / TPB, TPB>>>(H + O_MW1, H + O_R1, H + O_MW0, 32, 128, 128, wA);
        k_psub<<<GI, TPB>>>();
        k_bc_p<<<GP, TPB>>>(H + O_P, H + O_PPb);
        k_pupdate<<<GI, TPB>>>(wA);
    }

    // velocity correction + outputs
    k_bc_p<<<GP, TPB>>>(H + O_P, H + O_PPb);
    k_final<<<GI, TPB>>>(w2, w3, w4, sg, dtp, out);
    cudaMemcpyAsync(out + 5LL * NI_, H + O_R5, L5_ * sizeof(float),
                    cudaMemcpyDeviceToDevice, 0);
}

// round 10
// speedup vs baseline: 1.0087x; 1.0087x over previous
#include <cuda_runtime.h>

// ---------------------------------------------------------------------------
// AI4Urban CFD step on 64x256x256 grid. All scratch in one __device__ heap.
// ---------------------------------------------------------------------------

#define TPB 256

constexpr int NZ_ = 64, NY_ = 256, NX_ = 256;
constexpr int NI_ = NZ_ * NY_ * NX_;            // 4194304 interior cells
constexpr int PZ_ = NZ_ + 2, PY_ = NY_ + 2, PX_ = NX_ + 2;
constexpr int SY_ = PX_;                         // 258
constexpr int SZ_ = PY_ * PX_;                   // 66564
constexpr int PT_ = PZ_ * SZ_;                   // 4393224 padded cells

constexpr float RE_ = 0.15f;
constexpr float DX_ = 1.0f;
constexpr float UB_ = -1.0f;

// multigrid level sizes (levels 1..5; level 0 = NI_)
constexpr int L1_ = 32 * 128 * 128;
constexpr int L2_ = 16 * 64 * 64;
constexpr int L3_ = 8 * 32 * 32;
constexpr int L4_ = 4 * 16 * 16;
constexpr int L5_ = 2 * 8 * 8;

// ----- heap layout ---------------------------------------------------------
constexpr long long O_UU  = 0;
constexpr long long O_VV  = O_UU  + PT_;
constexpr long long O_WW  = O_VV  + PT_;
constexpr long long O_PPb = O_WW  + PT_;
constexpr long long O_KUU = O_PPb + PT_;
constexpr long long O_KVV = O_KUU + PT_;
constexpr long long O_KWW = O_KVV + PT_;

constexpr long long O_U    = O_KWW + PT_;
constexpr long long O_V    = O_U    + NI_;
constexpr long long O_W    = O_V    + NI_;
constexpr long long O_BU   = O_W    + NI_;
constexpr long long O_BV   = O_BU   + NI_;
constexpr long long O_BW   = O_BV   + NI_;
constexpr long long O_GPX  = O_BW   + NI_;
constexpr long long O_GPY  = O_GPX  + NI_;
constexpr long long O_GPZ  = O_GPY  + NI_;
constexpr long long O_ADXU = O_GPZ  + NI_;
constexpr long long O_ADYU = O_ADXU + NI_;
constexpr long long O_ADZU = O_ADYU + NI_;
constexpr long long O_AD2U = O_ADZU + NI_;
constexpr long long O_ADXV = O_AD2U + NI_;
constexpr long long O_ADYV = O_ADXV + NI_;
constexpr long long O_ADZV = O_ADYV + NI_;
constexpr long long O_AD2V = O_ADZV + NI_;
constexpr long long O_ADXW = O_AD2V + NI_;
constexpr long long O_ADYW = O_ADXW + NI_;
constexpr long long O_ADZW = O_ADYW + NI_;
constexpr long long O_AD2W = O_ADZW + NI_;
constexpr long long O_KX   = O_AD2W + NI_;
constexpr long long O_KY   = O_KX   + NI_;
constexpr long long O_KZ   = O_KY   + NI_;
constexpr long long O_P    = O_KZ   + NI_;
constexpr long long O_RHS  = O_P    + NI_;
constexpr long long O_SCR  = O_RHS  + NI_;
constexpr long long O_R0   = O_SCR  + NI_;
constexpr long long O_MW0  = O_R0   + NI_;
constexpr long long O_R1   = O_MW0  + NI_;
constexpr long long O_R2   = O_R1   + L1_;
constexpr long long O_R3   = O_R2   + L2_;
constexpr long long O_R4   = O_R3   + L3_;
constexpr long long O_R5   = O_R4   + L4_;
constexpr long long O_MW1  = O_R5   + L5_;
constexpr long long O_MW2  = O_MW1  + L1_;
constexpr long long O_MW3  = O_MW2  + L2_;
constexpr long long O_MW4  = O_MW3  + L3_;
constexpr long long O_MW5  = O_MW4  + L4_;
constexpr long long HEAP_N = O_MW5  + L5_;

__device__ float g_heap[HEAP_N];
__device__ float g_dt_fb = 0.5f;   // fallback dt if not passed as input

// robust dt loader (handles dt stored as f32 or f64)
__device__ __forceinline__ float get_dt(const float* p) {
    float f = *p;
    if (f > 1e-20f && f < 1e20f) return f;
    return (float)(*(const double*)p);
}

__device__ __forceinline__ float conv27(const float* __restrict__ s, int p,
                                        const float* __restrict__ wt) {
    float acc = 0.f;
#pragma unroll
    for (int dz = 0; dz < 3; ++dz)
#pragma unroll
        for (int dy = 0; dy < 3; ++dy)
#pragma unroll
            for (int dx = 0; dx < 3; ++dx)
                acc = fmaf(__ldg(&wt[dz * 9 + dy * 3 + dx]),
                           s[p + (dz - 1) * SZ_ + (dy - 1) * SY_ + (dx - 1)], acc);
    return acc;
}

// ----- elementwise: solid body on inputs ------------------------------------
__global__ void k_solid(const float* __restrict__ su, const float* __restrict__ sv,
                        const float* __restrict__ sw, const float* __restrict__ sg,
                        const float* __restrict__ dtp) {
    int i = blockIdx.x * TPB + threadIdx.x;
    if (i >= NI_) return;
    float dt = get_dt(dtp);
    float s = 1.f / (1.f + dt * sg[i]);
    g_heap[O_U + i] = su[i] * s;
    g_heap[O_V + i] = sv[i] * s;
    g_heap[O_W + i] = sw[i] * s;
}

// ----- boundary-condition padded builds -------------------------------------
__global__ void k_bc_u(const float* __restrict__ s, float* __restrict__ d) {
    int idx = blockIdx.x * TPB + threadIdx.x;
    if (idx >= PT_) return;
    int z = idx / SZ_; int r = idx - z * SZ_; int y = r / SY_; int x = r - y * SY_;
    float val;
    if (z == 0) {
        val = 0.f;
    } else {
        int zz = (z == PZ_ - 1) ? (PZ_ - 2) : z;
        int yy = (y == 0) ? 1 : ((y == PY_ - 1) ? (PY_ - 2) : y);
        if (x == 0 || x == PX_ - 1) val = UB_;
        else val = s[((zz - 1) * NY_ + (yy - 1)) * NX_ + (x - 1)];
    }
    d[idx] = val;
}

__global__ void k_bc_v(const float* __restrict__ s, float* __restrict__ d) {
    int idx = blockIdx.x * TPB + threadIdx.x;
    if (idx >= PT_) return;
    int z = idx / SZ_; int r = idx - z * SZ_; int y = r / SY_; int x = r - y * SY_;
    float val = 0.f;
    if (z != 0) {
        int zz = (z == PZ_ - 1) ? (PZ_ - 2) : z;
        if (!(y == 0 || y == PY_ - 1 || x == 0 || x == PX_ - 1))
            val = s[((zz - 1) * NY_ + (y - 1)) * NX_ + (x - 1)];
    }
    d[idx] = val;
}

__global__ void k_bc_w(const float* __restrict__ s, float* __restrict__ d) {
    int idx = blockIdx.x * TPB + threadIdx.x;
    if (idx >= PT_) return;
    int z = idx / SZ_; int r = idx - z * SZ_; int y = r / SY_; int x = r - y * SY_;
    float val = 0.f;
    if (!(z == 0 || z == PZ_ - 1 || y == 0 || y == PY_ - 1 || x == 0 || x == PX_ - 1))
        val = s[((z - 1) * NY_ + (y - 1)) * NX_ + (x - 1)];
    d[idx] = val;
}

__global__ void k_bc_p(const float* __restrict__ s, float* __restrict__ d) {
    int idx = blockIdx.x * TPB + threadIdx.x;
    if (idx >= PT_) return;
    int z = idx / SZ_; int r = idx - z * SZ_; int y = r / SY_; int x = r - y * SY_;
    float val;
    if (x == PX_ - 1) {
        val = 0.f;
    } else {
        int zz = (z == 0) ? 1 : ((z == PZ_ - 1) ? (PZ_ - 2) : z);
        int yy = (y == 0) ? 1 : ((y == PY_ - 1) ? (PY_ - 2) : y);
        int xx = (x == 0) ? 1 : x;
        val = s[((zz - 1) * NY_ + (yy - 1)) * NX_ + (xx - 1)];
    }
    d[idx] = val;
}

// ----- fused 4-stencil (w1,w2,w3,w4) on one padded field --------------------
__global__ void k_stencil4(const float* __restrict__ src,
                           const float* __restrict__ wa, const float* __restrict__ wb,
                           const float* __restrict__ wc, const float* __restrict__ wd,
                           float* __restrict__ oa, float* __restrict__ ob,
                           float* __restrict__ oc, float* __restrict__ od) {
    int i = blockIdx.x * TPB + threadIdx.x;
    if (i >= NI_) return;
    int z = i / (NY_ * NX_); int r = i - z * NY_ * NX_; int y = r / NX_; int x = r - y * NX_;
    int p = (z + 1) * SZ_ + (y + 1) * SY_ + (x + 1);
    float n[27];
#pragma unroll
    for (int dz = 0; dz < 3; ++dz)
#pragma unroll
        for (int dy = 0; dy < 3; ++dy)
#pragma unroll
            for (int dx = 0; dx < 3; ++dx)
                n[dz * 9 + dy * 3 + dx] =
                    src[p + (dz - 1) * SZ_ + (dy - 1) * SY_ + (dx - 1)];
    float a = 0.f, b = 0.f, c = 0.f, d = 0.f;
#pragma unroll
    for (int k = 0; k < 27; ++k) {
        float nv = n[k];
        a = fmaf(__ldg(&wa[k]), nv, a);
        b = fmaf(__ldg(&wb[k]), nv, b);
        c = fmaf(__ldg(&wc[k]), nv, c);
        d = fmaf(__ldg(&wd[k]), nv, d);
    }
    oa[i] = a; ob[i] = b; oc[i] = c; od[i] = d;
}

// ----- k coefficients (all 3 fields) into padded buffers (halo = 0) ---------
__global__ void k_kcoef(const float* __restrict__ vu, const float* __restrict__ vv,
                        const float* __restrict__ vw, const float* __restrict__ k1,
                        const float* __restrict__ sg, const float* __restrict__ dtp) {
    int idx = blockIdx.x * TPB + threadIdx.x;
    if (idx >= PT_) return;
    int z = idx / SZ_; int r = idx - z * SZ_; int y = r / SY_; int x = r - y * SY_;
    if (z == 0 || z == PZ_ - 1 || y == 0 || y == PY_ - 1 || x == 0 || x == PX_ - 1) {
        g_heap[O_KUU + idx] = 0.f;
        g_heap[O_KVV + idx] = 0.f;
        g_heap[O_KWW + idx] = 0.f;
        return;
    }
    int i = ((z - 1) * NY_ + (y - 1)) * NX_ + (x - 1);
    float dt = get_dt(dtp);
    float inv = 1.f / (1.f + dt * sg[i]);
    float speed = (fabsf(vu[i]) + fabsf(vv[i]) + fabsf(vw[i])) * DX_;
    const float c = 1.f / (DX_ * DX_ * DX_);
    float lim = k1[i];
    {
        float num = 0.1f * DX_ * fabsf((1.f / 3.f) * c * speed * g_heap[O_AD2U + i]);
        float den = 0.001f + (fabsf(g_heap[O_ADXU + i]) * c + fabsf(g_heap[O_ADYU + i]) * c +
                              fabsf(g_heap[O_ADZU + i]) * c) * (1.f / 3.f);
        g_heap[O_KUU + idx] = fminf(num / den, lim) * inv;
    }
    {
        float num = 0.1f * DX_ * fabsf((1.f / 3.f) * c * speed * g_heap[O_AD2V + i]);
        float den = 0.001f + (fabsf(g_heap[O_ADXV + i]) * c + fabsf(g_heap[O_ADYV + i]) * c +
                              fabsf(g_heap[O_ADZV + i]) * c) * (1.f / 3.f);
        g_heap[O_KVV + idx] = fminf(num / den, lim) * inv;
    }
    {
        float num = 0.1f * DX_ * fabsf((1.f / 3.f) * c * speed * g_heap[O_AD2W + i]);
        float den = 0.001f + (fabsf(g_heap[O_ADXW + i]) * c + fabsf(g_heap[O_ADYW + i]) * c +
                              fabsf(g_heap[O_ADZW + i]) * c) * (1.f / 3.f);
        g_heap[O_KWW + idx] = fminf(num / den, lim) * inv;
    }
}

// ----- PG flux: 0.5*(k*AD2 + conv(f*k,w1) - f*conv(k,w1)) --------------------
__global__ void k_pgflux(const float* __restrict__ fpad, const float* __restrict__ kpad,
                         const float* __restrict__ ad2, const float* __restrict__ vel,
                         const float* __restrict__ w1p, float* __restrict__ out) {
    int i = blockIdx.x * TPB + threadIdx.x;
    if (i >= NI_) return;
    int z = i / (NY_ * NX_); int r = i - z * NY_ * NX_; int y = r / NX_; int x = r - y * NX_;
    int p = (z + 1) * SZ_ + (y + 1) * SY_ + (x + 1);
    float acc1 = 0.f, acc2 = 0.f;
#pragma unroll
    for (int dz = 0; dz < 3; ++dz)
#pragma unroll
        for (int dy = 0; dy < 3; ++dy)
#pragma unroll
            for (int dx = 0; dx < 3; ++dx) {
                int off = (dz - 1) * SZ_ + (dy - 1) * SY_ + (dx - 1);
                float wgt = __ldg(&w1p[dz * 9 + dy * 3 + dx]);
                float kv = kpad[p + off];
                acc1 = fmaf(wgt, fpad[p + off] * kv, acc1);
                acc2 = fmaf(wgt, kv, acc2);
            }
    float kc = kpad[p];
    out[i] = 0.5f * (kc * ad2[i] + acc1 - vel[i] * acc2);
}

// ----- predictor half step ---------------------------------------------------
__global__ void k_predictor(const float* __restrict__ sg, const float* __restrict__ dtp) {
    int i = blockIdx.x * TPB + threadIdx.x;
    if (i >= NI_) return;
    float dt = get_dt(dtp);
    float s = 1.f / (1.f + dt * sg[i]);
    float U = g_heap[O_U + i], V = g_heap[O_V + i], W = g_heap[O_W + i];
    g_heap[O_BU + i] = (U + 0.5f * dt * (RE_ * g_heap[O_AD2U + i] - U * g_heap[O_ADXU + i]
                          - V * g_heap[O_ADYU + i] - W * g_heap[O_ADZU + i])
                          + 0.5f * dt * g_heap[O_KX + i] - dt * g_heap[O_GPX + i]) * s;
    g_heap[O_BV + i] = (V + 0.5f * dt * (RE_ * g_heap[O_AD2V + i] - U * g_heap[O_ADXV + i]
                          - V * g_heap[O_ADYV + i] - W * g_heap[O_ADZV + i])
                          + 0.5f * dt * g_heap[O_KY + i] - dt * g_heap[O_GPY + i]) * s;
    g_heap[O_BW + i] = (W + 0.5f * dt * (RE_ * g_heap[O_AD2W + i] - U * g_heap[O_ADXW + i]
                          - V * g_heap[O_ADYW + i] - W * g_heap[O_ADZW + i])
                          + 0.5f * dt * g_heap[O_KZ + i] - dt * g_heap[O_GPZ + i]) * s;
}

// ----- corrector full step ----------------------------------------------------
__global__ void k_corrector(const float* __restrict__ sg, const float* __restrict__ dtp) {
    int i = blockIdx.x * TPB + threadIdx.x;
    if (i >= NI_) return;
    float dt = get_dt(dtp);
    float s = 1.f / (1.f + dt * sg[i]);
    float U = g_heap[O_U + i], V = g_heap[O_V + i], W = g_heap[O_W + i];
    float BU = g_heap[O_BU + i], BV = g_heap[O_BV + i], BW = g_heap[O_BW + i];
    g_heap[O_U + i] = (U + dt * (RE_ * g_heap[O_AD2U + i] - BU * g_heap[O_ADXU + i]
                         - BV * g_heap[O_ADYU + i] - BW * g_heap[O_ADZU + i]
                         + g_heap[O_KX + i]) - dt * g_heap[O_GPX + i]) * s;
    g_heap[O_V + i] = (V + dt * (RE_ * g_heap[O_AD2V + i] - BU * g_heap[O_ADXV + i]
                         - BV * g_heap[O_ADYV + i] - BW * g_heap[O_ADZV + i]
                         + g_heap[O_KY + i]) - dt * g_heap[O_GPY + i]) * s;
    g_heap[O_W + i] = (W + dt * (RE_ * g_heap[O_AD2W + i] - BU * g_heap[O_ADXW + i]
                         - BV * g_heap[O_ADYW + i] - BW * g_heap[O_ADZW + i]
                         + g_heap[O_KZ + i]) - dt * g_heap[O_GPZ + i]) * s;
}

// ----- multigrid RHS: b = -div(u)/dt ------------------------------------------
__global__ void k_divrhs(const float* __restrict__ w2, const float* __restrict__ w3,
                         const float* __restrict__ w4, const float* __restrict__ dtp) {
    int i = blockIdx.x * TPB + threadIdx.x;
    if (i >= NI_) return;
    int z = i / (NY_ * NX_); int r = i - z * NY_ * NX_; int y = r / NX_; int x = r - y * NX_;
    int p = (z + 1) * SZ_ + (y + 1) * SY_ + (x + 1);
    float a = conv27(g_heap + O_UU, p, w2);
    float b = conv27(g_heap + O_VV, p, w3);
    float c = conv27(g_heap + O_WW, p, w4);
    g_heap[O_RHS + i] = -(a + b + c) / get_dt(dtp);
}

// ----- residual level 0 ---------------------------------------------------------
__global__ void k_resid0(const float* __restrict__ wA) {
    int i = blockIdx.x * TPB + threadIdx.x;
    if (i >= NI_) return;
    int z = i / (NY_ * NX_); int r = i - z * NY_ * NX_; int y = r / NX_; int x = r - y * NX_;
    int p = (z + 1) * SZ_ + (y + 1) * SY_ + (x + 1);
    g_heap[O_R0 + i] = conv27(g_heap + O_PPb, p, wA) - g_heap[O_RHS + i];
}

// ----- restriction (2x2x2 weighted avg, stride 2) -------------------------------
__global__ void k_restrict(const float* __restrict__ fine, float* __restrict__ coarse,
                           int cz, int cy, int cx, const float* __restrict__ wr) {
    int n = cz * cy * cx;
    int i = blockIdx.x * TPB + threadIdx.x;
    if (i >= n) return;
    int z = i / (cy * cx); int r = i - z * cy * cx; int y = r / cx; int x = r - y * cx;
    int fsy = 2 * cx;
    int fsz = fsy * 2 * cy;
    int base = (2 * z) * fsz + (2 * y) * fsy + 2 * x;
    float acc = 0.f;
#pragma unroll
    for (int jz = 0; jz < 2; ++jz)
#pragma unroll
        for (int jy = 0; jy < 2; ++jy)
#pragma unroll
            for (int jx = 0; jx < 2; ++jx)
                acc = fmaf(__ldg(&wr[jz * 4 + jy * 2 + jx]),
                           fine[base + jz * fsz + jy * fsy + jx], acc);
    coarse[i] = acc;
}

// ----- fused Jacobi smooth + prolongation ---------------------------------------
__global__ void k_smooth_prol(const float* __restrict__ wc, const float* __restrict__ rr,
                              float* __restrict__ wn, int dzs, int dys, int dxs,
                              const float* __restrict__ wA) {
    int n = dzs * dys * dxs;
    int i = blockIdx.x * TPB + threadIdx.x;
    if (i >= n) return;
    int z = i / (dys * dxs); int r = i - z * dys * dxs; int y = r / dxs; int x = r - y * dxs;
    float diag = __ldg(&wA[13]);
    float acc = 0.f;
#pragma unroll
    for (int dz = -1; dz <= 1; ++dz)
#pragma unroll
        for (int dy = -1; dy <= 1; ++dy)
#pragma unroll
            for (int dx = -1; dx <= 1; ++dx) {
                int zz = z + dz, yy = y + dy, xx = x + dx;
                float v = 0.f;
                if (zz >= 0 && zz < dzs && yy >= 0 && yy < dys && xx >= 0 && xx < dxs)
                    v = wc[(zz * dys + yy) * dxs + xx];
                acc = fmaf(__ldg(&wA[(dz + 1) * 9 + (dy + 1) * 3 + (dx + 1)]), v, acc);
            }
    float val = wc[i] - acc / diag + rr[i] / diag;
    int fsy = 2 * dxs;
    int fsz = fsy * 2 * dys;
    int fb = (2 * z) * fsz + (2 * y) * fsy + 2 * x;
    wn[fb] = val;             wn[fb + 1] = val;
    wn[fb + fsy] = val;       wn[fb + fsy + 1] = val;
    wn[fb + fsz] = val;       wn[fb + fsz + 1] = val;
    wn[fb + fsz + fsy] = val; wn[fb + fsz + fsy + 1] = val;
}

// ----- p -= w0 -------------------------------------------------------------------
__global__ void k_psub() {
    int i = blockIdx.x * TPB + threadIdx.x;
    if (i >= NI_) return;
    g_heap[O_P + i] -= g_heap[O_MW0 + i];
}

// ----- p = p - conv(pp,wA)/diag + rhs/diag ----------------------------------------
__global__ void k_pupdate(const float* __restrict__ wA) {
    int i = blockIdx.x * TPB + threadIdx.x;
    if (i >= NI_) return;
    int z = i / (NY_ * NX_); int r = i - z * NY_ * NX_; int y = r / NX_; int x = r - y * NX_;
    int p = (z + 1) * SZ_ + (y + 1) * SY_ + (x + 1);
    float diag = __ldg(&wA[13]);
    float cv = conv27(g_heap + O_PPb, p, wA);
    g_heap[O_P + i] = g_heap[O_P + i] - cv / diag + g_heap[O_RHS + i] / diag;
}

// ----- final: u -= grad(p)*dt, solid_body, write outputs --------------------------
__global__ void k_final(const float* __restrict__ w2, const float* __restrict__ w3,
                        const float* __restrict__ w4, const float* __restrict__ sg,
                        const float* __restrict__ dtp, float* __restrict__ out) {
    int i = blockIdx.x * TPB + threadIdx.x;
    if (i >= NI_) return;
    int z = i / (NY_ * NX_); int r = i - z * NY_ * NX_; int y = r / NX_; int x = r - y * NX_;
    int p = (z + 1) * SZ_ + (y + 1) * SY_ + (x + 1);
    float n[27];
#pragma unroll
    for (int dz = 0; dz < 3; ++dz)
#pragma unroll
        for (int dy = 0; dy < 3; ++dy)
#pragma unroll
            for (int dx = 0; dx < 3; ++dx)
                n[dz * 9 + dy * 3 + dx] =
                    g_heap[O_PPb + p + (dz - 1) * SZ_ + (dy - 1) * SY_ + (dx - 1)];
    float gx = 0.f, gy = 0.f, gz = 0.f;
#pragma unroll
    for (int k = 0; k < 27; ++k) {
        float nv = n[k];
        gx = fmaf(__ldg(&w2[k]), nv, gx);
        gy = fmaf(__ldg(&w3[k]), nv, gy);
        gz = fmaf(__ldg(&w4[k]), nv, gz);
    }
    float dt = get_dt(dtp);
    float s = 1.f / (1.f + dt * sg[i]);
    out[i] = (g_heap[O_U + i] - dt * gx) * s;
    out[(long long)NI_ + i] = (g_heap[O_V + i] - dt * gy) * s;
    out[2LL * NI_ + i] = (g_heap[O_W + i] - dt * gz) * s;
    out[3LL * NI_ + i] = g_heap[O_P + i];
    out[4LL * NI_ + i] = g_heap[O_MW0 + i];
}

// ---------------------------------------------------------------------------
extern "C" void kernel_launch(void* const* d_in, const int* in_sizes, int n_in,
                              void* d_out, int out_size) {
    const float* in_u = (const float*)d_in[0];
    const float* in_v = (const float*)d_in[2];
    const float* in_w = (const float*)d_in[4];
    const float* in_p = (const float*)d_in[6];
    const float* k1   = (const float*)d_in[11];
    const float* sg   = (const float*)d_in[15];
    const float* wA   = (const float*)d_in[16];
    const float* w1   = (const float*)d_in[17];
    const float* w2   = (const float*)d_in[18];
    const float* w3   = (const float*)d_in[19];
    const float* w4   = (const float*)d_in[20];
    const float* wres = (const float*)d_in[21];

    float* H = nullptr;
    cudaGetSymbolAddress((void**)&H, g_heap);

    const float* dtp;
    if (n_in > 22) {
        dtp = (const float*)d_in[22];
    } else {
        float* fb = nullptr;
        cudaGetSymbolAddress((void**)&fb, g_dt_fb);
        dtp = fb;
    }

    float* out = (float*)d_out;
    const int GI = (NI_ + TPB - 1) / TPB;
    const int GP = (PT_ + TPB - 1) / TPB;

    // stage A: solid body, BCs, stencils, PG, predictor
    k_solid<<<GI, TPB>>>(in_u, in_v, in_w, sg, dtp);
    k_bc_u<<<GP, TPB>>>(H + O_U, H + O_UU);
    k_bc_v<<<GP, TPB>>>(H + O_V, H + O_VV);
    k_bc_w<<<GP, TPB>>>(H + O_W, H + O_WW);
    k_bc_p<<<GP, TPB>>>(in_p, H + O_PPb);
    k_stencil4<<<GI, TPB>>>(H + O_UU, w1, w2, w3, w4, H + O_AD2U, H + O_ADXU, H + O_ADYU, H + O_ADZU);
    k_stencil4<<<GI, TPB>>>(H + O_VV, w1, w2, w3, w4, H + O_AD2V, H + O_ADXV, H + O_ADYV, H + O_ADZV);
    k_stencil4<<<GI, TPB>>>(H + O_WW, w1, w2, w3, w4, H + O_AD2W, H + O_ADXW, H + O_ADYW, H + O_ADZW);
    k_stencil4<<<GI, TPB>>>(H + O_PPb, w1, w2, w3, w4, H + O_SCR, H + O_GPX, H + O_GPY, H + O_GPZ);
    k_kcoef<<<GP, TPB>>>(H + O_U, H + O_V, H + O_W, k1, sg, dtp);
    k_pgflux<<<GI, TPB>>>(H + O_UU, H + O_KUU, H + O_AD2U, H + O_U, w1, H + O_KX);
    k_pgflux<<<GI, TPB>>>(H + O_VV, H + O_KVV, H + O_AD2V, H + O_V, w1, H + O_KY);
    k_pgflux<<<GI, TPB>>>(H + O_WW, H + O_KWW, H + O_AD2W, H + O_W, w1, H + O_KZ);
    k_predictor<<<GI, TPB>>>(sg, dtp);

    // stage B: BCs on predictor, stencils, PG, corrector
    k_bc_u<<<GP, TPB>>>(H + O_BU, H + O_UU);
    k_bc_v<<<GP, TPB>>>(H + O_BV, H + O_VV);
    k_bc_w<<<GP, TPB>>>(H + O_BW, H + O_WW);
    k_stencil4<<<GI, TPB>>>(H + O_UU, w1, w2, w3, w4, H + O_AD2U, H + O_ADXU, H + O_ADYU, H + O_ADZU);
    k_stencil4<<<GI, TPB>>>(H + O_VV, w1, w2, w3, w4, H + O_AD2V, H + O_ADXV, H + O_ADYV, H + O_ADZV);
    k_stencil4<<<GI, TPB>>>(H + O_WW, w1, w2, w3, w4, H + O_AD2W, H + O_ADXW, H + O_ADYW, H + O_ADZW);
    k_kcoef<<<GP, TPB>>>(H + O_BU, H + O_BV, H + O_BW, k1, sg, dtp);
    k_pgflux<<<GI, TPB>>>(H + O_UU, H + O_KUU, H + O_AD2U, H + O_BU, w1, H + O_KX);
    k_pgflux<<<GI, TPB>>>(H + O_VV, H + O_KVV, H + O_AD2V, H + O_BV, w1, H + O_KY);
    k_pgflux<<<GI, TPB>>>(H + O_WW, H + O_KWW, H + O_AD2W, H + O_BW, w1, H + O_KZ);
    k_corrector<<<GI, TPB>>>(sg, dtp);

    // final BCs + multigrid pressure solve
    k_bc_u<<<GP, TPB>>>(H + O_U, H + O_UU);
    k_bc_v<<<GP, TPB>>>(H + O_V, H + O_VV);
    k_bc_w<<<GP, TPB>>>(H + O_W, H + O_WW);
    k_divrhs<<<GI, TPB>>>(w2, w3, w4, dtp);
    cudaMemcpyAsync(H + O_P, in_p, (size_t)NI_ * sizeof(float), cudaMemcpyDeviceToDevice, 0);

    for (int it = 0; it < 2; ++it) {   // ITERATION = 2 (fixed by problem)
        k_bc_p<<<GP, TPB>>>(H + O_P, H + O_PPb);
        k_resid0<<<GI, TPB>>>(wA);
        k_restrict<<<(L1_ + TPB - 1) / TPB, TPB>>>(H + O_R0, H + O_R1, 32, 128, 128, wres);
        k_restrict<<<(L2_ + TPB - 1) / TPB, TPB>>>(H + O_R1, H + O_R2, 16, 64, 64, wres);
        k_restrict<<<(L3_ + TPB - 1) / TPB, TPB>>>(H + O_R2, H + O_R3, 8, 32, 32, wres);
        k_restrict<<<(L4_ + TPB - 1) / TPB, TPB>>>(H + O_R3, H + O_R4, 4, 16, 16, wres);
        k_restrict<<<1, TPB>>>(H + O_R4, H + O_R5, 2, 8, 8, wres);
        cudaMemsetAsync(H + O_MW5, 0, L5_ * sizeof(float), 0);
        k_smooth_prol<<<1, TPB>>>(H + O_MW5, H + O_R5, H + O_MW4, 2, 8, 8, wA);
        k_smooth_prol<<<(L4_ + TPB - 1) / TPB, TPB>>>(H + O_MW4, H + O_R4, H + O_MW3, 4, 16, 16, wA);
        k_smooth_prol<<<(L3_ + TPB - 1) / TPB, TPB>>>(H + O_MW3, H + O_R3, H + O_MW2, 8, 32, 32, wA);
        k_smooth_prol<<<(L2_ + TPB - 1) / TPB, TPB>>>(H + O_MW2, H + O_R2, H + O_MW1, 16, 64, 64, wA);
        k_smooth_prol<<<(L1_ + TPB - 1) / TPB, TPB>>>(H + O_MW1, H + O_R1, H + O_MW0, 32, 128, 128, wA);
        k_psub<<<GI, TPB>>>();
        k_bc_p<<<GP, TPB>>>(H + O_P, H + O_PPb);
        k_pupdate<<<GI, TPB>>>(wA);
    }

    // velocity correction + outputs
    k_bc_p<<<GP, TPB>>>(H + O_P, H + O_PPb);
    k_final<<<GI, TPB>>>(w2, w3, w4, sg, dtp, out);
    cudaMemcpyAsync(out + 5LL * NI_, H + O_R5, L5_ * sizeof(float),
                    cudaMemcpyDeviceToDevice, 0);
}

// round 11
// speedup vs baseline: 1.0096x; 1.0009x over previous
#include <cuda_runtime.h>

// ---------------------------------------------------------------------------
// AI4Urban CFD step on 64x256x256 grid. All scratch in one __device__ heap.
// ---------------------------------------------------------------------------

#define TPB 256

constexpr int NZ_ = 64, NY_ = 256, NX_ = 256;
constexpr int NI_ = NZ_ * NY_ * NX_;            // 4194304 interior cells
constexpr int PZ_ = NZ_ + 2, PY_ = NY_ + 2, PX_ = NX_ + 2;
constexpr int SY_ = PX_;                         // 258
constexpr int SZ_ = PY_ * PX_;                   // 66564
constexpr int PT_ = PZ_ * SZ_;                   // 4393224 padded cells

constexpr float RE_ = 0.15f;
constexpr float DX_ = 1.0f;
constexpr float UB_ = -1.0f;

// multigrid level sizes (levels 1..5; level 0 = NI_)
constexpr int L1_ = 32 * 128 * 128;
constexpr int L2_ = 16 * 64 * 64;
constexpr int L3_ = 8 * 32 * 32;
constexpr int L4_ = 4 * 16 * 16;
constexpr int L5_ = 2 * 8 * 8;

// ----- heap layout ---------------------------------------------------------
constexpr long long O_UU  = 0;
constexpr long long O_VV  = O_UU  + PT_;
constexpr long long O_WW  = O_VV  + PT_;
constexpr long long O_PPb = O_WW  + PT_;
constexpr long long O_KUU = O_PPb + PT_;
constexpr long long O_KVV = O_KUU + PT_;
constexpr long long O_KWW = O_KVV + PT_;

constexpr long long O_U    = O_KWW + PT_;
constexpr long long O_V    = O_U    + NI_;
constexpr long long O_W    = O_V    + NI_;
constexpr long long O_BU   = O_W    + NI_;
constexpr long long O_BV   = O_BU   + NI_;
constexpr long long O_BW   = O_BV   + NI_;
constexpr long long O_GPX  = O_BW   + NI_;
constexpr long long O_GPY  = O_GPX  + NI_;
constexpr long long O_GPZ  = O_GPY  + NI_;
constexpr long long O_ADXU = O_GPZ  + NI_;
constexpr long long O_ADYU = O_ADXU + NI_;
constexpr long long O_ADZU = O_ADYU + NI_;
constexpr long long O_AD2U = O_ADZU + NI_;
constexpr long long O_ADXV = O_AD2U + NI_;
constexpr long long O_ADYV = O_ADXV + NI_;
constexpr long long O_ADZV = O_ADYV + NI_;
constexpr long long O_AD2V = O_ADZV + NI_;
constexpr long long O_ADXW = O_AD2V + NI_;
constexpr long long O_ADYW = O_ADXW + NI_;
constexpr long long O_ADZW = O_ADYW + NI_;
constexpr long long O_AD2W = O_ADZW + NI_;
constexpr long long O_KX   = O_AD2W + NI_;
constexpr long long O_KY   = O_KX   + NI_;
constexpr long long O_KZ   = O_KY   + NI_;
constexpr long long O_P    = O_KZ   + NI_;
constexpr long long O_RHS  = O_P    + NI_;
constexpr long long O_SCR  = O_RHS  + NI_;
constexpr long long O_R0   = O_SCR  + NI_;
constexpr long long O_MW0  = O_R0   + NI_;
constexpr long long O_R1   = O_MW0  + NI_;
constexpr long long O_R2   = O_R1   + L1_;
constexpr long long O_R3   = O_R2   + L2_;
constexpr long long O_R4   = O_R3   + L3_;
constexpr long long O_R5   = O_R4   + L4_;
constexpr long long O_MW1  = O_R5   + L5_;
constexpr long long O_MW2  = O_MW1  + L1_;
constexpr long long O_MW3  = O_MW2  + L2_;
constexpr long long O_MW4  = O_MW3  + L3_;
constexpr long long O_MW5  = O_MW4  + L4_;
constexpr long long HEAP_N = O_MW5  + L5_;

__device__ float g_heap[HEAP_N];
__device__ float g_dt_fb = 0.5f;   // fallback dt if not passed as input

// robust dt loader (handles dt stored as f32 or f64)
__device__ __forceinline__ float get_dt(const float* p) {
    float f = *p;
    if (f > 1e-20f && f < 1e20f) return f;
    return (float)(*(const double*)p);
}

__device__ __forceinline__ float conv27(const float* __restrict__ s, int p,
                                        const float* __restrict__ wt) {
    float acc = 0.f;
#pragma unroll
    for (int dz = 0; dz < 3; ++dz)
#pragma unroll
        for (int dy = 0; dy < 3; ++dy)
#pragma unroll
            for (int dx = 0; dx < 3; ++dx)
                acc = fmaf(__ldg(&wt[dz * 9 + dy * 3 + dx]),
                           s[p + (dz - 1) * SZ_ + (dy - 1) * SY_ + (dx - 1)], acc);
    return acc;
}

// ----- elementwise: solid body on inputs ------------------------------------
__global__ void k_solid(const float* __restrict__ su, const float* __restrict__ sv,
                        const float* __restrict__ sw, const float* __restrict__ sg,
                        const float* __restrict__ dtp) {
    int i = blockIdx.x * TPB + threadIdx.x;
    if (i >= NI_) return;
    float dt = get_dt(dtp);
    float s = 1.f / (1.f + dt * sg[i]);
    g_heap[O_U + i] = su[i] * s;
    g_heap[O_V + i] = sv[i] * s;
    g_heap[O_W + i] = sw[i] * s;
}

// ----- boundary-condition padded builds -------------------------------------
__global__ void k_bc_u(const float* __restrict__ s, float* __restrict__ d) {
    int idx = blockIdx.x * TPB + threadIdx.x;
    if (idx >= PT_) return;
    int z = idx / SZ_; int r = idx - z * SZ_; int y = r / SY_; int x = r - y * SY_;
    float val;
    if (z == 0) {
        val = 0.f;
    } else {
        int zz = (z == PZ_ - 1) ? (PZ_ - 2) : z;
        int yy = (y == 0) ? 1 : ((y == PY_ - 1) ? (PY_ - 2) : y);
        if (x == 0 || x == PX_ - 1) val = UB_;
        else val = s[((zz - 1) * NY_ + (yy - 1)) * NX_ + (x - 1)];
    }
    d[idx] = val;
}

__global__ void k_bc_v(const float* __restrict__ s, float* __restrict__ d) {
    int idx = blockIdx.x * TPB + threadIdx.x;
    if (idx >= PT_) return;
    int z = idx / SZ_; int r = idx - z * SZ_; int y = r / SY_; int x = r - y * SY_;
    float val = 0.f;
    if (z != 0) {
        int zz = (z == PZ_ - 1) ? (PZ_ - 2) : z;
        if (!(y == 0 || y == PY_ - 1 || x == 0 || x == PX_ - 1))
            val = s[((zz - 1) * NY_ + (y - 1)) * NX_ + (x - 1)];
    }
    d[idx] = val;
}

__global__ void k_bc_w(const float* __restrict__ s, float* __restrict__ d) {
    int idx = blockIdx.x * TPB + threadIdx.x;
    if (idx >= PT_) return;
    int z = idx / SZ_; int r = idx - z * SZ_; int y = r / SY_; int x = r - y * SY_;
    float val = 0.f;
    if (!(z == 0 || z == PZ_ - 1 || y == 0 || y == PY_ - 1 || x == 0 || x == PX_ - 1))
        val = s[((z - 1) * NY_ + (y - 1)) * NX_ + (x - 1)];
    d[idx] = val;
}

__global__ void k_bc_p(const float* __restrict__ s, float* __restrict__ d) {
    int idx = blockIdx.x * TPB + threadIdx.x;
    if (idx >= PT_) return;
    int z = idx / SZ_; int r = idx - z * SZ_; int y = r / SY_; int x = r - y * SY_;
    float val;
    if (x == PX_ - 1) {
        val = 0.f;
    } else {
        int zz = (z == 0) ? 1 : ((z == PZ_ - 1) ? (PZ_ - 2) : z);
        int yy = (y == 0) ? 1 : ((y == PY_ - 1) ? (PY_ - 2) : y);
        int xx = (x == 0) ? 1 : x;
        val = s[((zz - 1) * NY_ + (yy - 1)) * NX_ + (xx - 1)];
    }
    d[idx] = val;
}

// ----- fused 4-stencil (w1,w2,w3,w4) on one padded field --------------------
__global__ void k_stencil4(const float* __restrict__ src,
                           const float* __restrict__ wa, const float* __restrict__ wb,
                           const float* __restrict__ wc, const float* __restrict__ wd,
                           float* __restrict__ oa, float* __restrict__ ob,
                           float* __restrict__ oc, float* __restrict__ od) {
    int i = blockIdx.x * TPB + threadIdx.x;
    if (i >= NI_) return;
    int z = i / (NY_ * NX_); int r = i - z * NY_ * NX_; int y = r / NX_; int x = r - y * NX_;
    int p = (z + 1) * SZ_ + (y + 1) * SY_ + (x + 1);
    float n[27];
#pragma unroll
    for (int dz = 0; dz < 3; ++dz)
#pragma unroll
        for (int dy = 0; dy < 3; ++dy)
#pragma unroll
            for (int dx = 0; dx < 3; ++dx)
                n[dz * 9 + dy * 3 + dx] =
                    src[p + (dz - 1) * SZ_ + (dy - 1) * SY_ + (dx - 1)];
    float a = 0.f, b = 0.f, c = 0.f, d = 0.f;
#pragma unroll
    for (int k = 0; k < 27; ++k) {
        float nv = n[k];
        a = fmaf(__ldg(&wa[k]), nv, a);
        b = fmaf(__ldg(&wb[k]), nv, b);
        c = fmaf(__ldg(&wc[k]), nv, c);
        d = fmaf(__ldg(&wd[k]), nv, d);
    }
    oa[i] = a; ob[i] = b; oc[i] = c; od[i] = d;
}

// ----- k coefficients (all 3 fields) into padded buffers (halo = 0) ---------
__global__ void k_kcoef(const float* __restrict__ vu, const float* __restrict__ vv,
                        const float* __restrict__ vw, const float* __restrict__ k1,
                        const float* __restrict__ sg, const float* __restrict__ dtp) {
    int idx = blockIdx.x * TPB + threadIdx.x;
    if (idx >= PT_) return;
    int z = idx / SZ_; int r = idx - z * SZ_; int y = r / SY_; int x = r - y * SY_;
    if (z == 0 || z == PZ_ - 1 || y == 0 || y == PY_ - 1 || x == 0 || x == PX_ - 1) {
        g_heap[O_KUU + idx] = 0.f;
        g_heap[O_KVV + idx] = 0.f;
        g_heap[O_KWW + idx] = 0.f;
        return;
    }
    int i = ((z - 1) * NY_ + (y - 1)) * NX_ + (x - 1);
    float dt = get_dt(dtp);
    float inv = 1.f / (1.f + dt * sg[i]);
    float speed = (fabsf(vu[i]) + fabsf(vv[i]) + fabsf(vw[i])) * DX_;
    const float c = 1.f / (DX_ * DX_ * DX_);
    float lim = k1[i];
    {
        float num = 0.1f * DX_ * fabsf((1.f / 3.f) * c * speed * g_heap[O_AD2U + i]);
        float den = 0.001f + (fabsf(g_heap[O_ADXU + i]) * c + fabsf(g_heap[O_ADYU + i]) * c +
                              fabsf(g_heap[O_ADZU + i]) * c) * (1.f / 3.f);
        g_heap[O_KUU + idx] = fminf(num / den, lim) * inv;
    }
    {
        float num = 0.1f * DX_ * fabsf((1.f / 3.f) * c * speed * g_heap[O_AD2V + i]);
        float den = 0.001f + (fabsf(g_heap[O_ADXV + i]) * c + fabsf(g_heap[O_ADYV + i]) * c +
                              fabsf(g_heap[O_ADZV + i]) * c) * (1.f / 3.f);
        g_heap[O_KVV + idx] = fminf(num / den, lim) * inv;
    }
    {
        float num = 0.1f * DX_ * fabsf((1.f / 3.f) * c * speed * g_heap[O_AD2W + i]);
        float den = 0.001f + (fabsf(g_heap[O_ADXW + i]) * c + fabsf(g_heap[O_ADYW + i]) * c +
                              fabsf(g_heap[O_ADZW + i]) * c) * (1.f / 3.f);
        g_heap[O_KWW + idx] = fminf(num / den, lim) * inv;
    }
}

// ----- PG flux: 0.5*(k*AD2 + conv(f*k,w1) - f*conv(k,w1)) --------------------
__global__ void k_pgflux(const float* __restrict__ fpad, const float* __restrict__ kpad,
                         const float* __restrict__ ad2, const float* __restrict__ vel,
                         const float* __restrict__ w1p, float* __restrict__ out) {
    int i = blockIdx.x * TPB + threadIdx.x;
    if (i >= NI_) return;
    int z = i / (NY_ * NX_); int r = i - z * NY_ * NX_; int y = r / NX_; int x = r - y * NX_;
    int p = (z + 1) * SZ_ + (y + 1) * SY_ + (x + 1);
    float acc1 = 0.f, acc2 = 0.f;
#pragma unroll
    for (int dz = 0; dz < 3; ++dz)
#pragma unroll
        for (int dy = 0; dy < 3; ++dy)
#pragma unroll
            for (int dx = 0; dx < 3; ++dx) {
                int off = (dz - 1) * SZ_ + (dy - 1) * SY_ + (dx - 1);
                float wgt = __ldg(&w1p[dz * 9 + dy * 3 + dx]);
                float kv = kpad[p + off];
                acc1 = fmaf(wgt, fpad[p + off] * kv, acc1);
                acc2 = fmaf(wgt, kv, acc2);
            }
    float kc = kpad[p];
    out[i] = 0.5f * (kc * ad2[i] + acc1 - vel[i] * acc2);
}

// ----- predictor half step ---------------------------------------------------
__global__ void k_predictor(const float* __restrict__ sg, const float* __restrict__ dtp) {
    int i = blockIdx.x * TPB + threadIdx.x;
    if (i >= NI_) return;
    float dt = get_dt(dtp);
    float s = 1.f / (1.f + dt * sg[i]);
    float U = g_heap[O_U + i], V = g_heap[O_V + i], W = g_heap[O_W + i];
    g_heap[O_BU + i] = (U + 0.5f * dt * (RE_ * g_heap[O_AD2U + i] - U * g_heap[O_ADXU + i]
                          - V * g_heap[O_ADYU + i] - W * g_heap[O_ADZU + i])
                          + 0.5f * dt * g_heap[O_KX + i] - dt * g_heap[O_GPX + i]) * s;
    g_heap[O_BV + i] = (V + 0.5f * dt * (RE_ * g_heap[O_AD2V + i] - U * g_heap[O_ADXV + i]
                          - V * g_heap[O_ADYV + i] - W * g_heap[O_ADZV + i])
                          + 0.5f * dt * g_heap[O_KY + i] - dt * g_heap[O_GPY + i]) * s;
    g_heap[O_BW + i] = (W + 0.5f * dt * (RE_ * g_heap[O_AD2W + i] - U * g_heap[O_ADXW + i]
                          - V * g_heap[O_ADYW + i] - W * g_heap[O_ADZW + i])
                          + 0.5f * dt * g_heap[O_KZ + i] - dt * g_heap[O_GPZ + i]) * s;
}

// ----- corrector full step ----------------------------------------------------
__global__ void k_corrector(const float* __restrict__ sg, const float* __restrict__ dtp) {
    int i = blockIdx.x * TPB + threadIdx.x;
    if (i >= NI_) return;
    float dt = get_dt(dtp);
    float s = 1.f / (1.f + dt * sg[i]);
    float U = g_heap[O_U + i], V = g_heap[O_V + i], W = g_heap[O_W + i];
    float BU = g_heap[O_BU + i], BV = g_heap[O_BV + i], BW = g_heap[O_BW + i];
    g_heap[O_U + i] = (U + dt * (RE_ * g_heap[O_AD2U + i] - BU * g_heap[O_ADXU + i]
                         - BV * g_heap[O_ADYU + i] - BW * g_heap[O_ADZU + i]
                         + g_heap[O_KX + i]) - dt * g_heap[O_GPX + i]) * s;
    g_heap[O_V + i] = (V + dt * (RE_ * g_heap[O_AD2V + i] - BU * g_heap[O_ADXV + i]
                         - BV * g_heap[O_ADYV + i] - BW * g_heap[O_ADZV + i]
                         + g_heap[O_KY + i]) - dt * g_heap[O_GPY + i]) * s;
    g_heap[O_W + i] = (W + dt * (RE_ * g_heap[O_AD2W + i] - BU * g_heap[O_ADXW + i]
                         - BV * g_heap[O_ADYW + i] - BW * g_heap[O_ADZW + i]
                         + g_heap[O_KZ + i]) - dt * g_heap[O_GPZ + i]) * s;
}

// ----- multigrid RHS: b = -div(u)/dt ------------------------------------------
__global__ void k_divrhs(const float* __restrict__ w2, const float* __restrict__ w3,
                         const float* __restrict__ w4, const float* __restrict__ dtp) {
    int i = blockIdx.x * TPB + threadIdx.x;
    if (i >= NI_) return;
    int z = i / (NY_ * NX_); int r = i - z * NY_ * NX_; int y = r / NX_; int x = r - y * NX_;
    int p = (z + 1) * SZ_ + (y + 1) * SY_ + (x + 1);
    float a = conv27(g_heap + O_UU, p, w2);
    float b = conv27(g_heap + O_VV, p, w3);
    float c = conv27(g_heap + O_WW, p, w4);
    g_heap[O_RHS + i] = -(a + b + c) / get_dt(dtp);
}

// ----- residual level 0 ---------------------------------------------------------
__global__ void k_resid0(const float* __restrict__ wA) {
    int i = blockIdx.x * TPB + threadIdx.x;
    if (i >= NI_) return;
    int z = i / (NY_ * NX_); int r = i - z * NY_ * NX_; int y = r / NX_; int x = r - y * NX_;
    int p = (z + 1) * SZ_ + (y + 1) * SY_ + (x + 1);
    g_heap[O_R0 + i] = conv27(g_heap + O_PPb, p, wA) - g_heap[O_RHS + i];
}

// ----- restriction (2x2x2 weighted avg, stride 2) -------------------------------
__global__ void k_restrict(const float* __restrict__ fine, float* __restrict__ coarse,
                           int cz, int cy, int cx, const float* __restrict__ wr) {
    int n = cz * cy * cx;
    int i = blockIdx.x * TPB + threadIdx.x;
    if (i >= n) return;
    int z = i / (cy * cx); int r = i - z * cy * cx; int y = r / cx; int x = r - y * cx;
    int fsy = 2 * cx;
    int fsz = fsy * 2 * cy;
    int base = (2 * z) * fsz + (2 * y) * fsy + 2 * x;
    float acc = 0.f;
#pragma unroll
    for (int jz = 0; jz < 2; ++jz)
#pragma unroll
        for (int jy = 0; jy < 2; ++jy)
#pragma unroll
            for (int jx = 0; jx < 2; ++jx)
                acc = fmaf(__ldg(&wr[jz * 4 + jy * 2 + jx]),
                           fine[base + jz * fsz + jy * fsy + jx], acc);
    coarse[i] = acc;
}

// ----- fused Jacobi smooth + prolongation ---------------------------------------
__global__ void k_smooth_prol(const float* __restrict__ wc, const float* __restrict__ rr,
                              float* __restrict__ wn, int dzs, int dys, int dxs,
                              const float* __restrict__ wA) {
    int n = dzs * dys * dxs;
    int i = blockIdx.x * TPB + threadIdx.x;
    if (i >= n) return;
    int z = i / (dys * dxs); int r = i - z * dys * dxs; int y = r / dxs; int x = r - y * dxs;
    float diag = __ldg(&wA[13]);
    float acc = 0.f;
#pragma unroll
    for (int dz = -1; dz <= 1; ++dz)
#pragma unroll
        for (int dy = -1; dy <= 1; ++dy)
#pragma unroll
            for (int dx = -1; dx <= 1; ++dx) {
                int zz = z + dz, yy = y + dy, xx = x + dx;
                float v = 0.f;
                if (zz >= 0 && zz < dzs && yy >= 0 && yy < dys && xx >= 0 && xx < dxs)
                    v = wc[(zz * dys + yy) * dxs + xx];
                acc = fmaf(__ldg(&wA[(dz + 1) * 9 + (dy + 1) * 3 + (dx + 1)]), v, acc);
            }
    float val = wc[i] - acc / diag + rr[i] / diag;
    int fsy = 2 * dxs;
    int fsz = fsy * 2 * dys;
    int fb = (2 * z) * fsz + (2 * y) * fsy + 2 * x;
    wn[fb] = val;             wn[fb + 1] = val;
    wn[fb + fsy] = val;       wn[fb + fsy + 1] = val;
    wn[fb + fsz] = val;       wn[fb + fsz + 1] = val;
    wn[fb + fsz + fsy] = val; wn[fb + fsz + fsy + 1] = val;
}

// ----- p -= w0 -------------------------------------------------------------------
__global__ void k_psub() {
    int i = blockIdx.x * TPB + threadIdx.x;
    if (i >= NI_) return;
    g_heap[O_P + i] -= g_heap[O_MW0 + i];
}

// ----- p = p - conv(pp,wA)/diag + rhs/diag ----------------------------------------
__global__ void k_pupdate(const float* __restrict__ wA) {
    int i = blockIdx.x * TPB + threadIdx.x;
    if (i >= NI_) return;
    int z = i / (NY_ * NX_); int r = i - z * NY_ * NX_; int y = r / NX_; int x = r - y * NX_;
    int p = (z + 1) * SZ_ + (y + 1) * SY_ + (x + 1);
    float diag = __ldg(&wA[13]);
    float cv = conv27(g_heap + O_PPb, p, wA);
    g_heap[O_P + i] = g_heap[O_P + i] - cv / diag + g_heap[O_RHS + i] / diag;
}

// ----- final: u -= grad(p)*dt, solid_body, write outputs --------------------------
__global__ void k_final(const float* __restrict__ w2, const float* __restrict__ w3,
                        const float* __restrict__ w4, const float* __restrict__ sg,
                        const float* __restrict__ dtp, float* __restrict__ out) {
    int i = blockIdx.x * TPB + threadIdx.x;
    if (i >= NI_) return;
    int z = i / (NY_ * NX_); int r = i - z * NY_ * NX_; int y = r / NX_; int x = r - y * NX_;
    int p = (z + 1) * SZ_ + (y + 1) * SY_ + (x + 1);
    float n[27];
#pragma unroll
    for (int dz = 0; dz < 3; ++dz)
#pragma unroll
        for (int dy = 0; dy < 3; ++dy)
#pragma unroll
            for (int dx = 0; dx < 3; ++dx)
                n[dz * 9 + dy * 3 + dx] =
                    g_heap[O_PPb + p + (dz - 1) * SZ_ + (dy - 1) * SY_ + (dx - 1)];
    float gx = 0.f, gy = 0.f, gz = 0.f;
#pragma unroll
    for (int k = 0; k < 27; ++k) {
        float nv = n[k];
        gx = fmaf(__ldg(&w2[k]), nv, gx);
        gy = fmaf(__ldg(&w3[k]), nv, gy);
        gz = fmaf(__ldg(&w4[k]), nv, gz);
    }
    float dt = get_dt(dtp);
    float s = 1.f / (1.f + dt * sg[i]);
    out[i] = (g_heap[O_U + i] - dt * gx) * s;
    out[(long long)NI_ + i] = (g_heap[O_V + i] - dt * gy) * s;
    out[2LL * NI_ + i] = (g_heap[O_W + i] - dt * gz) * s;
    out[3LL * NI_ + i] = g_heap[O_P + i];
    out[4LL * NI_ + i] = g_heap[O_MW0 + i];
}

// ---------------------------------------------------------------------------
extern "C" void kernel_launch(void* const* d_in, const int* in_sizes, int n_in,
                              void* d_out, int out_size) {
    const float* in_u = (const float*)d_in[0];
    const float* in_v = (const float*)d_in[2];
    const float* in_w = (const float*)d_in[4];
    const float* in_p = (const float*)d_in[6];
    const float* k1   = (const float*)d_in[11];
    const float* sg   = (const float*)d_in[15];
    const float* wA   = (const float*)d_in[16];
    const float* w1   = (const float*)d_in[17];
    const float* w2   = (const float*)d_in[18];
    const float* w3   = (const float*)d_in[19];
    const float* w4   = (const float*)d_in[20];
    const float* wres = (const float*)d_in[21];

    float* H = nullptr;
    cudaGetSymbolAddress((void**)&H, g_heap);

    const float* dtp;
    if (n_in > 22) {
        dtp = (const float*)d_in[22];
    } else {
        float* fb = nullptr;
        cudaGetSymbolAddress((void**)&fb, g_dt_fb);
        dtp = fb;
    }

    float* out = (float*)d_out;
    const int GI = (NI_ + TPB - 1) / TPB;
    const int GP = (PT_ + TPB - 1) / TPB;

    // stage A: solid body, BCs, stencils, PG, predictor
    k_solid<<<GI, TPB>>>(in_u, in_v, in_w, sg, dtp);
    k_bc_u<<<GP, TPB>>>(H + O_U, H + O_UU);
    k_bc_v<<<GP, TPB>>>(H + O_V, H + O_VV);
    k_bc_w<<<GP, TPB>>>(H + O_W, H + O_WW);
    k_bc_p<<<GP, TPB>>>(in_p, H + O_PPb);
    k_stencil4<<<GI, TPB>>>(H + O_UU, w1, w2, w3, w4, H + O_AD2U, H + O_ADXU, H + O_ADYU, H + O_ADZU);
    k_stencil4<<<GI, TPB>>>(H + O_VV, w1, w2, w3, w4, H + O_AD2V, H + O_ADXV, H + O_ADYV, H + O_ADZV);
    k_stencil4<<<GI, TPB>>>(H + O_WW, w1, w2, w3, w4, H + O_AD2W, H + O_ADXW, H + O_ADYW, H + O_ADZW);
    k_stencil4<<<GI, TPB>>>(H + O_PPb, w1, w2, w3, w4, H + O_SCR, H + O_GPX, H + O_GPY, H + O_GPZ);
    k_kcoef<<<GP, TPB>>>(H + O_U, H + O_V, H + O_W, k1, sg, dtp);
    k_pgflux<<<GI, TPB>>>(H + O_UU, H + O_KUU, H + O_AD2U, H + O_U, w1, H + O_KX);
    k_pgflux<<<GI, TPB>>>(H + O_VV, H + O_KVV, H + O_AD2V, H + O_V, w1, H + O_KY);
    k_pgflux<<<GI, TPB>>>(H + O_WW, H + O_KWW, H + O_AD2W, H + O_W, w1, H + O_KZ);
    k_predictor<<<GI, TPB>>>(sg, dtp);

    // stage B: BCs on predictor, stencils, PG, corrector
    k_bc_u<<<GP, TPB>>>(H + O_BU, H + O_UU);
    k_bc_v<<<GP, TPB>>>(H + O_BV, H + O_VV);
    k_bc_w<<<GP, TPB>>>(H + O_BW, H + O_WW);
    k_stencil4<<<GI, TPB>>>(H + O_UU, w1, w2, w3, w4, H + O_AD2U, H + O_ADXU, H + O_ADYU, H + O_ADZU);
    k_stencil4<<<GI, TPB>>>(H + O_VV, w1, w2, w3, w4, H + O_AD2V, H + O_ADXV, H + O_ADYV, H + O_ADZV);
    k_stencil4<<<GI, TPB>>>(H + O_WW, w1, w2, w3, w4, H + O_AD2W, H + O_ADXW, H + O_ADYW, H + O_ADZW);
    k_kcoef<<<GP, TPB>>>(H + O_BU, H + O_BV, H + O_BW, k1, sg, dtp);
    k_pgflux<<<GI, TPB>>>(H + O_UU, H + O_KUU, H + O_AD2U, H + O_BU, w1, H + O_KX);
    k_pgflux<<<GI, TPB>>>(H + O_VV, H + O_KVV, H + O_AD2V, H + O_BV, w1, H + O_KY);
    k_pgflux<<<GI, TPB>>>(H + O_WW, H + O_KWW, H + O_AD2W, H + O_BW, w1, H + O_KZ);
    k_corrector<<<GI, TPB>>>(sg, dtp);

    // final BCs + multigrid pressure solve
    k_bc_u<<<GP, TPB>>>(H + O_U, H + O_UU);
    k_bc_v<<<GP, TPB>>>(H + O_V, H + O_VV);
    k_bc_w<<<GP, TPB>>>(H + O_W, H + O_WW);
    k_divrhs<<<GI, TPB>>>(w2, w3, w4, dtp);
    cudaMemcpyAsync(H + O_P, in_p, (size_t)NI_ * sizeof(float), cudaMemcpyDeviceToDevice, 0);

    for (int it = 0; it < 2; ++it) {   // ITERATION = 2 (fixed by problem)
        k_bc_p<<<GP, TPB>>>(H + O_P, H + O_PPb);
        k_resid0<<<GI, TPB>>>(wA);
        k_restrict<<<(L1_ + TPB - 1) / TPB, TPB>>>(H + O_R0, H + O_R1, 32, 128, 128, wres);
        k_restrict<<<(L2_ + TPB - 1) / TPB, TPB>>>(H + O_R1, H + O_R2, 16, 64, 64, wres);
        k_restrict<<<(L3_ + TPB - 1) / TPB, TPB>>>(H + O_R2, H + O_R3, 8, 32, 32, wres);
        k_restrict<<<(L4_ + TPB - 1) / TPB, TPB>>>(H + O_R3, H + O_R4, 4, 16, 16, wres);
        k_restrict<<<1, TPB>>>(H + O_R4, H + O_R5, 2, 8, 8, wres);
        cudaMemsetAsync(H + O_MW5, 0, L5_ * sizeof(float), 0);
        k_smooth_prol<<<1, TPB>>>(H + O_MW5, H + O_R5, H + O_MW4, 2, 8, 8, wA);
        k_smooth_prol<<<(L4_ + TPB - 1) / TPB, TPB>>>(H + O_MW4, H + O_R4, H + O_MW3, 4, 16, 16, wA);
        k_smooth_prol<<<(L3_ + TPB - 1) / TPB, TPB>>>(H + O_MW3, H + O_R3, H + O_MW2, 8, 32, 32, wA);
        k_smooth_prol<<<(L2_ + TPB - 1) / TPB, TPB>>>(H + O_MW2, H + O_R2, H + O_MW1, 16, 64, 64, wA);
        k_smooth_prol<<<(L1_ + TPB - 1) / TPB, TPB>>>(H + O_MW1, H + O_R1, H + O_MW0, 32, 128, 128, wA);
        k_psub<<<GI, TPB>>>();
        k_bc_p<<<GP, TPB>>>(H + O_P, H + O_PPb);
        k_pupdate<<<GI, TPB>>>(wA);
    }

    // velocity correction + outputs
    k_bc_p<<<GP, TPB>>>(H + O_P, H + O_PPb);
    k_final<<<GI, TPB>>>(w2, w3, w4, sg, dtp, out);
    cudaMemcpyAsync(out + 5LL * NI_, H + O_R5, L5_ * sizeof(float),
                    cudaMemcpyDeviceToDevice, 0);
}

// round 12
// speedup vs baseline: 1.0097x; 1.0000x over previous
#include <cuda_runtime.h>

// ---------------------------------------------------------------------------
// AI4Urban CFD step on 64x256x256 grid. All scratch in one __device__ heap.
// ---------------------------------------------------------------------------

#define TPB 256

constexpr int NZ_ = 64, NY_ = 256, NX_ = 256;
constexpr int NI_ = NZ_ * NY_ * NX_;            // 4194304 interior cells
constexpr int PZ_ = NZ_ + 2, PY_ = NY_ + 2, PX_ = NX_ + 2;
constexpr int SY_ = PX_;                         // 258
constexpr int SZ_ = PY_ * PX_;                   // 66564
constexpr int PT_ = PZ_ * SZ_;                   // 4393224 padded cells

constexpr float RE_ = 0.15f;
constexpr float DX_ = 1.0f;
constexpr float UB_ = -1.0f;

// multigrid level sizes (levels 1..5; level 0 = NI_)
constexpr int L1_ = 32 * 128 * 128;
constexpr int L2_ = 16 * 64 * 64;
constexpr int L3_ = 8 * 32 * 32;
constexpr int L4_ = 4 * 16 * 16;
constexpr int L5_ = 2 * 8 * 8;

// ----- heap layout ---------------------------------------------------------
constexpr long long O_UU  = 0;
constexpr long long O_VV  = O_UU  + PT_;
constexpr long long O_WW  = O_VV  + PT_;
constexpr long long O_PPb = O_WW  + PT_;
constexpr long long O_KUU = O_PPb + PT_;
constexpr long long O_KVV = O_KUU + PT_;
constexpr long long O_KWW = O_KVV + PT_;

constexpr long long O_U    = O_KWW + PT_;
constexpr long long O_V    = O_U    + NI_;
constexpr long long O_W    = O_V    + NI_;
constexpr long long O_BU   = O_W    + NI_;
constexpr long long O_BV   = O_BU   + NI_;
constexpr long long O_BW   = O_BV   + NI_;
constexpr long long O_GPX  = O_BW   + NI_;
constexpr long long O_GPY  = O_GPX  + NI_;
constexpr long long O_GPZ  = O_GPY  + NI_;
constexpr long long O_ADXU = O_GPZ  + NI_;
constexpr long long O_ADYU = O_ADXU + NI_;
constexpr long long O_ADZU = O_ADYU + NI_;
constexpr long long O_AD2U = O_ADZU + NI_;
constexpr long long O_ADXV = O_AD2U + NI_;
constexpr long long O_ADYV = O_ADXV + NI_;
constexpr long long O_ADZV = O_ADYV + NI_;
constexpr long long O_AD2V = O_ADZV + NI_;
constexpr long long O_ADXW = O_AD2V + NI_;
constexpr long long O_ADYW = O_ADXW + NI_;
constexpr long long O_ADZW = O_ADYW + NI_;
constexpr long long O_AD2W = O_ADZW + NI_;
constexpr long long O_KX   = O_AD2W + NI_;
constexpr long long O_KY   = O_KX   + NI_;
constexpr long long O_KZ   = O_KY   + NI_;
constexpr long long O_P    = O_KZ   + NI_;
constexpr long long O_RHS  = O_P    + NI_;
constexpr long long O_SCR  = O_RHS  + NI_;
constexpr long long O_R0   = O_SCR  + NI_;
constexpr long long O_MW0  = O_R0   + NI_;
constexpr long long O_R1   = O_MW0  + NI_;
constexpr long long O_R2   = O_R1   + L1_;
constexpr long long O_R3   = O_R2   + L2_;
constexpr long long O_R4   = O_R3   + L3_;
constexpr long long O_R5   = O_R4   + L4_;
constexpr long long O_MW1  = O_R5   + L5_;
constexpr long long O_MW2  = O_MW1  + L1_;
constexpr long long O_MW3  = O_MW2  + L2_;
constexpr long long O_MW4  = O_MW3  + L3_;
constexpr long long O_MW5  = O_MW4  + L4_;
constexpr long long HEAP_N = O_MW5  + L5_;

__device__ float g_heap[HEAP_N];
__device__ float g_dt_fb = 0.5f;   // fallback dt if not passed as input

// robust dt loader (handles dt stored as f32 or f64)
__device__ __forceinline__ float get_dt(const float* p) {
    float f = *p;
    if (f > 1e-20f && f < 1e20f) return f;
    return (float)(*(const double*)p);
}

__device__ __forceinline__ float conv27(const float* __restrict__ s, int p,
                                        const float* __restrict__ wt) {
    float acc = 0.f;
#pragma unroll
    for (int dz = 0; dz < 3; ++dz)
#pragma unroll
        for (int dy = 0; dy < 3; ++dy)
#pragma unroll
            for (int dx = 0; dx < 3; ++dx)
                acc = fmaf(__ldg(&wt[dz * 9 + dy * 3 + dx]),
                           s[p + (dz - 1) * SZ_ + (dy - 1) * SY_ + (dx - 1)], acc);
    return acc;
}

// ----- elementwise: solid body on inputs ------------------------------------
__global__ void k_solid(const float* __restrict__ su, const float* __restrict__ sv,
                        const float* __restrict__ sw, const float* __restrict__ sg,
                        const float* __restrict__ dtp) {
    int i = blockIdx.x * TPB + threadIdx.x;
    if (i >= NI_) return;
    float dt = get_dt(dtp);
    float s = 1.f / (1.f + dt * sg[i]);
    g_heap[O_U + i] = su[i] * s;
    g_heap[O_V + i] = sv[i] * s;
    g_heap[O_W + i] = sw[i] * s;
}

// ----- boundary-condition padded builds -------------------------------------
__global__ void k_bc_u(const float* __restrict__ s, float* __restrict__ d) {
    int idx = blockIdx.x * TPB + threadIdx.x;
    if (idx >= PT_) return;
    int z = idx / SZ_; int r = idx - z * SZ_; int y = r / SY_; int x = r - y * SY_;
    float val;
    if (z == 0) {
        val = 0.f;
    } else {
        int zz = (z == PZ_ - 1) ? (PZ_ - 2) : z;
        int yy = (y == 0) ? 1 : ((y == PY_ - 1) ? (PY_ - 2) : y);
        if (x == 0 || x == PX_ - 1) val = UB_;
        else val = s[((zz - 1) * NY_ + (yy - 1)) * NX_ + (x - 1)];
    }
    d[idx] = val;
}

__global__ void k_bc_v(const float* __restrict__ s, float* __restrict__ d) {
    int idx = blockIdx.x * TPB + threadIdx.x;
    if (idx >= PT_) return;
    int z = idx / SZ_; int r = idx - z * SZ_; int y = r / SY_; int x = r - y * SY_;
    float val = 0.f;
    if (z != 0) {
        int zz = (z == PZ_ - 1) ? (PZ_ - 2) : z;
        if (!(y == 0 || y == PY_ - 1 || x == 0 || x == PX_ - 1))
            val = s[((zz - 1) * NY_ + (y - 1)) * NX_ + (x - 1)];
    }
    d[idx] = val;
}

__global__ void k_bc_w(const float* __restrict__ s, float* __restrict__ d) {
    int idx = blockIdx.x * TPB + threadIdx.x;
    if (idx >= PT_) return;
    int z = idx / SZ_; int r = idx - z * SZ_; int y = r / SY_; int x = r - y * SY_;
    float val = 0.f;
    if (!(z == 0 || z == PZ_ - 1 || y == 0 || y == PY_ - 1 || x == 0 || x == PX_ - 1))
        val = s[((z - 1) * NY_ + (y - 1)) * NX_ + (x - 1)];
    d[idx] = val;
}

__global__ void k_bc_p(const float* __restrict__ s, float* __restrict__ d) {
    int idx = blockIdx.x * TPB + threadIdx.x;
    if (idx >= PT_) return;
    int z = idx / SZ_; int r = idx - z * SZ_; int y = r / SY_; int x = r - y * SY_;
    float val;
    if (x == PX_ - 1) {
        val = 0.f;
    } else {
        int zz = (z == 0) ? 1 : ((z == PZ_ - 1) ? (PZ_ - 2) : z);
        int yy = (y == 0) ? 1 : ((y == PY_ - 1) ? (PY_ - 2) : y);
        int xx = (x == 0) ? 1 : x;
        val = s[((zz - 1) * NY_ + (yy - 1)) * NX_ + (xx - 1)];
    }
    d[idx] = val;
}

// ----- fused 4-stencil (w1,w2,w3,w4) on one padded field --------------------
__global__ void k_stencil4(const float* __restrict__ src,
                           const float* __restrict__ wa, const float* __restrict__ wb,
                           const float* __restrict__ wc, const float* __restrict__ wd,
                           float* __restrict__ oa, float* __restrict__ ob,
                           float* __restrict__ oc, float* __restrict__ od) {
    int i = blockIdx.x * TPB + threadIdx.x;
    if (i >= NI_) return;
    int z = i / (NY_ * NX_); int r = i - z * NY_ * NX_; int y = r / NX_; int x = r - y * NX_;
    int p = (z + 1) * SZ_ + (y + 1) * SY_ + (x + 1);
    float n[27];
#pragma unroll
    for (int dz = 0; dz < 3; ++dz)
#pragma unroll
        for (int dy = 0; dy < 3; ++dy)
#pragma unroll
            for (int dx = 0; dx < 3; ++dx)
                n[dz * 9 + dy * 3 + dx] =
                    src[p + (dz - 1) * SZ_ + (dy - 1) * SY_ + (dx - 1)];
    float a = 0.f, b = 0.f, c = 0.f, d = 0.f;
#pragma unroll
    for (int k = 0; k < 27; ++k) {
        float nv = n[k];
        a = fmaf(__ldg(&wa[k]), nv, a);
        b = fmaf(__ldg(&wb[k]), nv, b);
        c = fmaf(__ldg(&wc[k]), nv, c);
        d = fmaf(__ldg(&wd[k]), nv, d);
    }
    oa[i] = a; ob[i] = b; oc[i] = c; od[i] = d;
}

// ----- k coefficients (all 3 fields) into padded buffers (halo = 0) ---------
__global__ void k_kcoef(const float* __restrict__ vu, const float* __restrict__ vv,
                        const float* __restrict__ vw, const float* __restrict__ k1,
                        const float* __restrict__ sg, const float* __restrict__ dtp) {
    int idx = blockIdx.x * TPB + threadIdx.x;
    if (idx >= PT_) return;
    int z = idx / SZ_; int r = idx - z * SZ_; int y = r / SY_; int x = r - y * SY_;
    if (z == 0 || z == PZ_ - 1 || y == 0 || y == PY_ - 1 || x == 0 || x == PX_ - 1) {
        g_heap[O_KUU + idx] = 0.f;
        g_heap[O_KVV + idx] = 0.f;
        g_heap[O_KWW + idx] = 0.f;
        return;
    }
    int i = ((z - 1) * NY_ + (y - 1)) * NX_ + (x - 1);
    float dt = get_dt(dtp);
    float inv = 1.f / (1.f + dt * sg[i]);
    float speed = (fabsf(vu[i]) + fabsf(vv[i]) + fabsf(vw[i])) * DX_;
    const float c = 1.f / (DX_ * DX_ * DX_);
    float lim = k1[i];
    {
        float num = 0.1f * DX_ * fabsf((1.f / 3.f) * c * speed * g_heap[O_AD2U + i]);
        float den = 0.001f + (fabsf(g_heap[O_ADXU + i]) * c + fabsf(g_heap[O_ADYU + i]) * c +
                              fabsf(g_heap[O_ADZU + i]) * c) * (1.f / 3.f);
        g_heap[O_KUU + idx] = fminf(num / den, lim) * inv;
    }
    {
        float num = 0.1f * DX_ * fabsf((1.f / 3.f) * c * speed * g_heap[O_AD2V + i]);
        float den = 0.001f + (fabsf(g_heap[O_ADXV + i]) * c + fabsf(g_heap[O_ADYV + i]) * c +
                              fabsf(g_heap[O_ADZV + i]) * c) * (1.f / 3.f);
        g_heap[O_KVV + idx] = fminf(num / den, lim) * inv;
    }
    {
        float num = 0.1f * DX_ * fabsf((1.f / 3.f) * c * speed * g_heap[O_AD2W + i]);
        float den = 0.001f + (fabsf(g_heap[O_ADXW + i]) * c + fabsf(g_heap[O_ADYW + i]) * c +
                              fabsf(g_heap[O_ADZW + i]) * c) * (1.f / 3.f);
        g_heap[O_KWW + idx] = fminf(num / den, lim) * inv;
    }
}

// ----- PG flux: 0.5*(k*AD2 + conv(f*k,w1) - f*conv(k,w1)) --------------------
__global__ void k_pgflux(const float* __restrict__ fpad, const float* __restrict__ kpad,
                         const float* __restrict__ ad2, const float* __restrict__ vel,
                         const float* __restrict__ w1p, float* __restrict__ out) {
    int i = blockIdx.x * TPB + threadIdx.x;
    if (i >= NI_) return;
    int z = i / (NY_ * NX_); int r = i - z * NY_ * NX_; int y = r / NX_; int x = r - y * NX_;
    int p = (z + 1) * SZ_ + (y + 1) * SY_ + (x + 1);
    float acc1 = 0.f, acc2 = 0.f;
#pragma unroll
    for (int dz = 0; dz < 3; ++dz)
#pragma unroll
        for (int dy = 0; dy < 3; ++dy)
#pragma unroll
            for (int dx = 0; dx < 3; ++dx) {
                int off = (dz - 1) * SZ_ + (dy - 1) * SY_ + (dx - 1);
                float wgt = __ldg(&w1p[dz * 9 + dy * 3 + dx]);
                float kv = kpad[p + off];
                acc1 = fmaf(wgt, fpad[p + off] * kv, acc1);
                acc2 = fmaf(wgt, kv, acc2);
            }
    float kc = kpad[p];
    out[i] = 0.5f * (kc * ad2[i] + acc1 - vel[i] * acc2);
}

// ----- predictor half step ---------------------------------------------------
__global__ void k_predictor(const float* __restrict__ sg, const float* __restrict__ dtp) {
    int i = blockIdx.x * TPB + threadIdx.x;
    if (i >= NI_) return;
    float dt = get_dt(dtp);
    float s = 1.f / (1.f + dt * sg[i]);
    float U = g_heap[O_U + i], V = g_heap[O_V + i], W = g_heap[O_W + i];
    g_heap[O_BU + i] = (U + 0.5f * dt * (RE_ * g_heap[O_AD2U + i] - U * g_heap[O_ADXU + i]
                          - V * g_heap[O_ADYU + i] - W * g_heap[O_ADZU + i])
                          + 0.5f * dt * g_heap[O_KX + i] - dt * g_heap[O_GPX + i]) * s;
    g_heap[O_BV + i] = (V + 0.5f * dt * (RE_ * g_heap[O_AD2V + i] - U * g_heap[O_ADXV + i]
                          - V * g_heap[O_ADYV + i] - W * g_heap[O_ADZV + i])
                          + 0.5f * dt * g_heap[O_KY + i] - dt * g_heap[O_GPY + i]) * s;
    g_heap[O_BW + i] = (W + 0.5f * dt * (RE_ * g_heap[O_AD2W + i] - U * g_heap[O_ADXW + i]
                          - V * g_heap[O_ADYW + i] - W * g_heap[O_ADZW + i])
                          + 0.5f * dt * g_heap[O_KZ + i] - dt * g_heap[O_GPZ + i]) * s;
}

// ----- corrector full step ----------------------------------------------------
__global__ void k_corrector(const float* __restrict__ sg, const float* __restrict__ dtp) {
    int i = blockIdx.x * TPB + threadIdx.x;
    if (i >= NI_) return;
    float dt = get_dt(dtp);
    float s = 1.f / (1.f + dt * sg[i]);
    float U = g_heap[O_U + i], V = g_heap[O_V + i], W = g_heap[O_W + i];
    float BU = g_heap[O_BU + i], BV = g_heap[O_BV + i], BW = g_heap[O_BW + i];
    g_heap[O_U + i] = (U + dt * (RE_ * g_heap[O_AD2U + i] - BU * g_heap[O_ADXU + i]
                         - BV * g_heap[O_ADYU + i] - BW * g_heap[O_ADZU + i]
                         + g_heap[O_KX + i]) - dt * g_heap[O_GPX + i]) * s;
    g_heap[O_V + i] = (V + dt * (RE_ * g_heap[O_AD2V + i] - BU * g_heap[O_ADXV + i]
                         - BV * g_heap[O_ADYV + i] - BW * g_heap[O_ADZV + i]
                         + g_heap[O_KY + i]) - dt * g_heap[O_GPY + i]) * s;
    g_heap[O_W + i] = (W + dt * (RE_ * g_heap[O_AD2W + i] - BU * g_heap[O_ADXW + i]
                         - BV * g_heap[O_ADYW + i] - BW * g_heap[O_ADZW + i]
                         + g_heap[O_KZ + i]) - dt * g_heap[O_GPZ + i]) * s;
}

// ----- multigrid RHS: b = -div(u)/dt ------------------------------------------
__global__ void k_divrhs(const float* __restrict__ w2, const float* __restrict__ w3,
                         const float* __restrict__ w4, const float* __restrict__ dtp) {
    int i = blockIdx.x * TPB + threadIdx.x;
    if (i >= NI_) return;
    int z = i / (NY_ * NX_); int r = i - z * NY_ * NX_; int y = r / NX_; int x = r - y * NX_;
    int p = (z + 1) * SZ_ + (y + 1) * SY_ + (x + 1);
    float a = conv27(g_heap + O_UU, p, w2);
    float b = conv27(g_heap + O_VV, p, w3);
    float c = conv27(g_heap + O_WW, p, w4);
    g_heap[O_RHS + i] = -(a + b + c) / get_dt(dtp);
}

// ----- residual level 0 ---------------------------------------------------------
__global__ void k_resid0(const float* __restrict__ wA) {
    int i = blockIdx.x * TPB + threadIdx.x;
    if (i >= NI_) return;
    int z = i / (NY_ * NX_); int r = i - z * NY_ * NX_; int y = r / NX_; int x = r - y * NX_;
    int p = (z + 1) * SZ_ + (y + 1) * SY_ + (x + 1);
    g_heap[O_R0 + i] = conv27(g_heap + O_PPb, p, wA) - g_heap[O_RHS + i];
}

// ----- restriction (2x2x2 weighted avg, stride 2) -------------------------------
__global__ void k_restrict(const float* __restrict__ fine, float* __restrict__ coarse,
                           int cz, int cy, int cx, const float* __restrict__ wr) {
    int n = cz * cy * cx;
    int i = blockIdx.x * TPB + threadIdx.x;
    if (i >= n) return;
    int z = i / (cy * cx); int r = i - z * cy * cx; int y = r / cx; int x = r - y * cx;
    int fsy = 2 * cx;
    int fsz = fsy * 2 * cy;
    int base = (2 * z) * fsz + (2 * y) * fsy + 2 * x;
    float acc = 0.f;
#pragma unroll
    for (int jz = 0; jz < 2; ++jz)
#pragma unroll
        for (int jy = 0; jy < 2; ++jy)
#pragma unroll
            for (int jx = 0; jx < 2; ++jx)
                acc = fmaf(__ldg(&wr[jz * 4 + jy * 2 + jx]),
                           fine[base + jz * fsz + jy * fsy + jx], acc);
    coarse[i] = acc;
}

// ----- fused Jacobi smooth + prolongation ---------------------------------------
__global__ void k_smooth_prol(const float* __restrict__ wc, const float* __restrict__ rr,
                              float* __restrict__ wn, int dzs, int dys, int dxs,
                              const float* __restrict__ wA) {
    int n = dzs * dys * dxs;
    int i = blockIdx.x * TPB + threadIdx.x;
    if (i >= n) return;
    int z = i / (dys * dxs); int r = i - z * dys * dxs; int y = r / dxs; int x = r - y * dxs;
    float diag = __ldg(&wA[13]);
    float acc = 0.f;
#pragma unroll
    for (int dz = -1; dz <= 1; ++dz)
#pragma unroll
        for (int dy = -1; dy <= 1; ++dy)
#pragma unroll
            for (int dx = -1; dx <= 1; ++dx) {
                int zz = z + dz, yy = y + dy, xx = x + dx;
                float v = 0.f;
                if (zz >= 0 && zz < dzs && yy >= 0 && yy < dys && xx >= 0 && xx < dxs)
                    v = wc[(zz * dys + yy) * dxs + xx];
                acc = fmaf(__ldg(&wA[(dz + 1) * 9 + (dy + 1) * 3 + (dx + 1)]), v, acc);
            }
    float val = wc[i] - acc / diag + rr[i] / diag;
    int fsy = 2 * dxs;
    int fsz = fsy * 2 * dys;
    int fb = (2 * z) * fsz + (2 * y) * fsy + 2 * x;
    wn[fb] = val;             wn[fb + 1] = val;
    wn[fb + fsy] = val;       wn[fb + fsy + 1] = val;
    wn[fb + fsz] = val;       wn[fb + fsz + 1] = val;
    wn[fb + fsz + fsy] = val; wn[fb + fsz + fsy + 1] = val;
}

// ----- p -= w0 -------------------------------------------------------------------
__global__ void k_psub() {
    int i = blockIdx.x * TPB + threadIdx.x;
    if (i >= NI_) return;
    g_heap[O_P + i] -= g_heap[O_MW0 + i];
}

// ----- p = p - conv(pp,wA)/diag + rhs/diag ----------------------------------------
__global__ void k_pupdate(const float* __restrict__ wA) {
    int i = blockIdx.x * TPB + threadIdx.x;
    if (i >= NI_) return;
    int z = i / (NY_ * NX_); int r = i - z * NY_ * NX_; int y = r / NX_; int x = r - y * NX_;
    int p = (z + 1) * SZ_ + (y + 1) * SY_ + (x + 1);
    float diag = __ldg(&wA[13]);
    float cv = conv27(g_heap + O_PPb, p, wA);
    g_heap[O_P + i] = g_heap[O_P + i] - cv / diag + g_heap[O_RHS + i] / diag;
}

// ----- final: u -= grad(p)*dt, solid_body, write outputs --------------------------
__global__ void k_final(const float* __restrict__ w2, const float* __restrict__ w3,
                        const float* __restrict__ w4, const float* __restrict__ sg,
                        const float* __restrict__ dtp, float* __restrict__ out) {
    int i = blockIdx.x * TPB + threadIdx.x;
    if (i >= NI_) return;
    int z = i / (NY_ * NX_); int r = i - z * NY_ * NX_; int y = r / NX_; int x = r - y * NX_;
    int p = (z + 1) * SZ_ + (y + 1) * SY_ + (x + 1);
    float n[27];
#pragma unroll
    for (int dz = 0; dz < 3; ++dz)
#pragma unroll
        for (int dy = 0; dy < 3; ++dy)
#pragma unroll
            for (int dx = 0; dx < 3; ++dx)
                n[dz * 9 + dy * 3 + dx] =
                    g_heap[O_PPb + p + (dz - 1) * SZ_ + (dy - 1) * SY_ + (dx - 1)];
    float gx = 0.f, gy = 0.f, gz = 0.f;
#pragma unroll
    for (int k = 0; k < 27; ++k) {
        float nv = n[k];
        gx = fmaf(__ldg(&w2[k]), nv, gx);
        gy = fmaf(__ldg(&w3[k]), nv, gy);
        gz = fmaf(__ldg(&w4[k]), nv, gz);
    }
    float dt = get_dt(dtp);
    float s = 1.f / (1.f + dt * sg[i]);
    out[i] = (g_heap[O_U + i] - dt * gx) * s;
    out[(long long)NI_ + i] = (g_heap[O_V + i] - dt * gy) * s;
    out[2LL * NI_ + i] = (g_heap[O_W + i] - dt * gz) * s;
    out[3LL * NI_ + i] = g_heap[O_P + i];
    out[4LL * NI_ + i] = g_heap[O_MW0 + i];
}

// ---------------------------------------------------------------------------
extern "C" void kernel_launch(void* const* d_in, const int* in_sizes, int n_in,
                              void* d_out, int out_size) {
    const float* in_u = (const float*)d_in[0];
    const float* in_v = (const float*)d_in[2];
    const float* in_w = (const float*)d_in[4];
    const float* in_p = (const float*)d_in[6];
    const float* k1   = (const float*)d_in[11];
    const float* sg   = (const float*)d_in[15];
    const float* wA   = (const float*)d_in[16];
    const float* w1   = (const float*)d_in[17];
    const float* w2   = (const float*)d_in[18];
    const float* w3   = (const float*)d_in[19];
    const float* w4   = (const float*)d_in[20];
    const float* wres = (const float*)d_in[21];

    float* H = nullptr;
    cudaGetSymbolAddress((void**)&H, g_heap);

    const float* dtp;
    if (n_in > 22) {
        dtp = (const float*)d_in[22];
    } else {
        float* fb = nullptr;
        cudaGetSymbolAddress((void**)&fb, g_dt_fb);
        dtp = fb;
    }

    float* out = (float*)d_out;
    const int GI = (NI_ + TPB - 1) / TPB;
    const int GP = (PT_ + TPB - 1) / TPB;

    // stage A: solid body, BCs, stencils, PG, predictor
    k_solid<<<GI, TPB>>>(in_u, in_v, in_w, sg, dtp);
    k_bc_u<<<GP, TPB>>>(H + O_U, H + O_UU);
    k_bc_v<<<GP, TPB>>>(H + O_V, H + O_VV);
    k_bc_w<<<GP, TPB>>>(H + O_W, H + O_WW);
    k_bc_p<<<GP, TPB>>>(in_p, H + O_PPb);
    k_stencil4<<<GI, TPB>>>(H + O_UU, w1, w2, w3, w4, H + O_AD2U, H + O_ADXU, H + O_ADYU, H + O_ADZU);
    k_stencil4<<<GI, TPB>>>(H + O_VV, w1, w2, w3, w4, H + O_AD2V, H + O_ADXV, H + O_ADYV, H + O_ADZV);
    k_stencil4<<<GI, TPB>>>(H + O_WW, w1, w2, w3, w4, H + O_AD2W, H + O_ADXW, H + O_ADYW, H + O_ADZW);
    k_stencil4<<<GI, TPB>>>(H + O_PPb, w1, w2, w3, w4, H + O_SCR, H + O_GPX, H + O_GPY, H + O_GPZ);
    k_kcoef<<<GP, TPB>>>(H + O_U, H + O_V, H + O_W, k1, sg, dtp);
    k_pgflux<<<GI, TPB>>>(H + O_UU, H + O_KUU, H + O_AD2U, H + O_U, w1, H + O_KX);
    k_pgflux<<<GI, TPB>>>(H + O_VV, H + O_KVV, H + O_AD2V, H + O_V, w1, H + O_KY);
    k_pgflux<<<GI, TPB>>>(H + O_WW, H + O_KWW, H + O_AD2W, H + O_W, w1, H + O_KZ);
    k_predictor<<<GI, TPB>>>(sg, dtp);

    // stage B: BCs on predictor, stencils, PG, corrector
    k_bc_u<<<GP, TPB>>>(H + O_BU, H + O_UU);
    k_bc_v<<<GP, TPB>>>(H + O_BV, H + O_VV);
    k_bc_w<<<GP, TPB>>>(H + O_BW, H + O_WW);
    k_stencil4<<<GI, TPB>>>(H + O_UU, w1, w2, w3, w4, H + O_AD2U, H + O_ADXU, H + O_ADYU, H + O_ADZU);
    k_stencil4<<<GI, TPB>>>(H + O_VV, w1, w2, w3, w4, H + O_AD2V, H + O_ADXV, H + O_ADYV, H + O_ADZV);
    k_stencil4<<<GI, TPB>>>(H + O_WW, w1, w2, w3, w4, H + O_AD2W, H + O_ADXW, H + O_ADYW, H + O_ADZW);
    k_kcoef<<<GP, TPB>>>(H + O_BU, H + O_BV, H + O_BW, k1, sg, dtp);
    k_pgflux<<<GI, TPB>>>(H + O_UU, H + O_KUU, H + O_AD2U, H + O_BU, w1, H + O_KX);
    k_pgflux<<<GI, TPB>>>(H + O_VV, H + O_KVV, H + O_AD2V, H + O_BV, w1, H + O_KY);
    k_pgflux<<<GI, TPB>>>(H + O_WW, H + O_KWW, H + O_AD2W, H + O_BW, w1, H + O_KZ);
    k_corrector<<<GI, TPB>>>(sg, dtp);

    // final BCs + multigrid pressure solve
    k_bc_u<<<GP, TPB>>>(H + O_U, H + O_UU);
    k_bc_v<<<GP, TPB>>>(H + O_V, H + O_VV);
    k_bc_w<<<GP, TPB>>>(H + O_W, H + O_WW);
    k_divrhs<<<GI, TPB>>>(w2, w3, w4, dtp);
    cudaMemcpyAsync(H + O_P, in_p, (size_t)NI_ * sizeof(float), cudaMemcpyDeviceToDevice, 0);

    for (int it = 0; it < 2; ++it) {   // ITERATION = 2 (fixed by problem)
        k_bc_p<<<GP, TPB>>>(H + O_P, H + O_PPb);
        k_resid0<<<GI, TPB>>>(wA);
        k_restrict<<<(L1_ + TPB - 1) / TPB, TPB>>>(H + O_R0, H + O_R1, 32, 128, 128, wres);
        k_restrict<<<(L2_ + TPB - 1) / TPB, TPB>>>(H + O_R1, H + O_R2, 16, 64, 64, wres);
        k_restrict<<<(L3_ + TPB - 1) / TPB, TPB>>>(H + O_R2, H + O_R3, 8, 32, 32, wres);
        k_restrict<<<(L4_ + TPB - 1) / TPB, TPB>>>(H + O_R3, H + O_R4, 4, 16, 16, wres);
        k_restrict<<<1, TPB>>>(H + O_R4, H + O_R5, 2, 8, 8, wres);
        cudaMemsetAsync(H + O_MW5, 0, L5_ * sizeof(float), 0);
        k_smooth_prol<<<1, TPB>>>(H + O_MW5, H + O_R5, H + O_MW4, 2, 8, 8, wA);
        k_smooth_prol<<<(L4_ + TPB - 1) / TPB, TPB>>>(H + O_MW4, H + O_R4, H + O_MW3, 4, 16, 16, wA);
        k_smooth_prol<<<(L3_ + TPB - 1) / TPB, TPB>>>(H + O_MW3, H + O_R3, H + O_MW2, 8, 32, 32, wA);
        k_smooth_prol<<<(L2_ + TPB - 1) / TPB, TPB>>>(H + O_MW2, H + O_R2, H + O_MW1, 16, 64, 64, wA);
        k_smooth_prol<<<(L1_ + TPB - 1) / TPB, TPB>>>(H + O_MW1, H + O_R1, H + O_MW0, 32, 128, 128, wA);
        k_psub<<<GI, TPB>>>();
        k_bc_p<<<GP, TPB>>>(H + O_P, H + O_PPb);
        k_pupdate<<<GI, TPB>>>(wA);
    }

    // velocity correction + outputs
    k_bc_p<<<GP, TPB>>>(H + O_P, H + O_PPb);
    k_final<<<GI, TPB>>>(w2, w3, w4, sg, dtp, out);
    cudaMemcpyAsync(out + 5LL * NI_, H + O_R5, L5_ * sizeof(float),
                    cudaMemcpyDeviceToDevice, 0);
}

// round 13
// speedup vs baseline: 1.0099x; 1.0003x over previous
#include <cuda_runtime.h>

// ---------------------------------------------------------------------------
// AI4Urban CFD step on 64x256x256 grid. All scratch in one __device__ heap.
// ---------------------------------------------------------------------------

#define TPB 256

constexpr int NZ_ = 64, NY_ = 256, NX_ = 256;
constexpr int NI_ = NZ_ * NY_ * NX_;            // 4194304 interior cells
constexpr int PZ_ = NZ_ + 2, PY_ = NY_ + 2, PX_ = NX_ + 2;
constexpr int SY_ = PX_;                         // 258
constexpr int SZ_ = PY_ * PX_;                   // 66564
constexpr int PT_ = PZ_ * SZ_;                   // 4393224 padded cells

constexpr float RE_ = 0.15f;
constexpr float DX_ = 1.0f;
constexpr float UB_ = -1.0f;

// multigrid level sizes (levels 1..5; level 0 = NI_)
constexpr int L1_ = 32 * 128 * 128;
constexpr int L2_ = 16 * 64 * 64;
constexpr int L3_ = 8 * 32 * 32;
constexpr int L4_ = 4 * 16 * 16;
constexpr int L5_ = 2 * 8 * 8;

// ----- heap layout ---------------------------------------------------------
constexpr long long O_UU  = 0;
constexpr long long O_VV  = O_UU  + PT_;
constexpr long long O_WW  = O_VV  + PT_;
constexpr long long O_PPb = O_WW  + PT_;
constexpr long long O_KUU = O_PPb + PT_;
constexpr long long O_KVV = O_KUU + PT_;
constexpr long long O_KWW = O_KVV + PT_;

constexpr long long O_U    = O_KWW + PT_;
constexpr long long O_V    = O_U    + NI_;
constexpr long long O_W    = O_V    + NI_;
constexpr long long O_BU   = O_W    + NI_;
constexpr long long O_BV   = O_BU   + NI_;
constexpr long long O_BW   = O_BV   + NI_;
constexpr long long O_GPX  = O_BW   + NI_;
constexpr long long O_GPY  = O_GPX  + NI_;
constexpr long long O_GPZ  = O_GPY  + NI_;
constexpr long long O_ADXU = O_GPZ  + NI_;
constexpr long long O_ADYU = O_ADXU + NI_;
constexpr long long O_ADZU = O_ADYU + NI_;
constexpr long long O_AD2U = O_ADZU + NI_;
constexpr long long O_ADXV = O_AD2U + NI_;
constexpr long long O_ADYV = O_ADXV + NI_;
constexpr long long O_ADZV = O_ADYV + NI_;
constexpr long long O_AD2V = O_ADZV + NI_;
constexpr long long O_ADXW = O_AD2V + NI_;
constexpr long long O_ADYW = O_ADXW + NI_;
constexpr long long O_ADZW = O_ADYW + NI_;
constexpr long long O_AD2W = O_ADZW + NI_;
constexpr long long O_KX   = O_AD2W + NI_;
constexpr long long O_KY   = O_KX   + NI_;
constexpr long long O_KZ   = O_KY   + NI_;
constexpr long long O_P    = O_KZ   + NI_;
constexpr long long O_RHS  = O_P    + NI_;
constexpr long long O_SCR  = O_RHS  + NI_;
constexpr long long O_R0   = O_SCR  + NI_;
constexpr long long O_MW0  = O_R0   + NI_;
constexpr long long O_R1   = O_MW0  + NI_;
constexpr long long O_R2   = O_R1   + L1_;
constexpr long long O_R3   = O_R2   + L2_;
constexpr long long O_R4   = O_R3   + L3_;
constexpr long long O_R5   = O_R4   + L4_;
constexpr long long O_MW1  = O_R5   + L5_;
constexpr long long O_MW2  = O_MW1  + L1_;
constexpr long long O_MW3  = O_MW2  + L2_;
constexpr long long O_MW4  = O_MW3  + L3_;
constexpr long long O_MW5  = O_MW4  + L4_;
constexpr long long HEAP_N = O_MW5  + L5_;

__device__ float g_heap[HEAP_N];
__device__ float g_dt_fb = 0.5f;   // fallback dt if not passed as input

// robust dt loader (handles dt stored as f32 or f64)
__device__ __forceinline__ float get_dt(const float* p) {
    float f = *p;
    if (f > 1e-20f && f < 1e20f) return f;
    return (float)(*(const double*)p);
}

__device__ __forceinline__ float conv27(const float* __restrict__ s, int p,
                                        const float* __restrict__ wt) {
    float acc = 0.f;
#pragma unroll
    for (int dz = 0; dz < 3; ++dz)
#pragma unroll
        for (int dy = 0; dy < 3; ++dy)
#pragma unroll
            for (int dx = 0; dx < 3; ++dx)
                acc = fmaf(__ldg(&wt[dz * 9 + dy * 3 + dx]),
                           s[p + (dz - 1) * SZ_ + (dy - 1) * SY_ + (dx - 1)], acc);
    return acc;
}

// ----- elementwise: solid body on inputs ------------------------------------
__global__ void k_solid(const float* __restrict__ su, const float* __restrict__ sv,
                        const float* __restrict__ sw, const float* __restrict__ sg,
                        const float* __restrict__ dtp) {
    int i = blockIdx.x * TPB + threadIdx.x;
    if (i >= NI_) return;
    float dt = get_dt(dtp);
    float s = 1.f / (1.f + dt * sg[i]);
    g_heap[O_U + i] = su[i] * s;
    g_heap[O_V + i] = sv[i] * s;
    g_heap[O_W + i] = sw[i] * s;
}

// ----- boundary-condition padded builds -------------------------------------
__global__ void k_bc_u(const float* __restrict__ s, float* __restrict__ d) {
    int idx = blockIdx.x * TPB + threadIdx.x;
    if (idx >= PT_) return;
    int z = idx / SZ_; int r = idx - z * SZ_; int y = r / SY_; int x = r - y * SY_;
    float val;
    if (z == 0) {
        val = 0.f;
    } else {
        int zz = (z == PZ_ - 1) ? (PZ_ - 2) : z;
        int yy = (y == 0) ? 1 : ((y == PY_ - 1) ? (PY_ - 2) : y);
        if (x == 0 || x == PX_ - 1) val = UB_;
        else val = s[((zz - 1) * NY_ + (yy - 1)) * NX_ + (x - 1)];
    }
    d[idx] = val;
}

__global__ void k_bc_v(const float* __restrict__ s, float* __restrict__ d) {
    int idx = blockIdx.x * TPB + threadIdx.x;
    if (idx >= PT_) return;
    int z = idx / SZ_; int r = idx - z * SZ_; int y = r / SY_; int x = r - y * SY_;
    float val = 0.f;
    if (z != 0) {
        int zz = (z == PZ_ - 1) ? (PZ_ - 2) : z;
        if (!(y == 0 || y == PY_ - 1 || x == 0 || x == PX_ - 1))
            val = s[((zz - 1) * NY_ + (y - 1)) * NX_ + (x - 1)];
    }
    d[idx] = val;
}

__global__ void k_bc_w(const float* __restrict__ s, float* __restrict__ d) {
    int idx = blockIdx.x * TPB + threadIdx.x;
    if (idx >= PT_) return;
    int z = idx / SZ_; int r = idx - z * SZ_; int y = r / SY_; int x = r - y * SY_;
    float val = 0.f;
    if (!(z == 0 || z == PZ_ - 1 || y == 0 || y == PY_ - 1 || x == 0 || x == PX_ - 1))
        val = s[((z - 1) * NY_ + (y - 1)) * NX_ + (x - 1)];
    d[idx] = val;
}

__global__ void k_bc_p(const float* __restrict__ s, float* __restrict__ d) {
    int idx = blockIdx.x * TPB + threadIdx.x;
    if (idx >= PT_) return;
    int z = idx / SZ_; int r = idx - z * SZ_; int y = r / SY_; int x = r - y * SY_;
    float val;
    if (x == PX_ - 1) {
        val = 0.f;
    } else {
        int zz = (z == 0) ? 1 : ((z == PZ_ - 1) ? (PZ_ - 2) : z);
        int yy = (y == 0) ? 1 : ((y == PY_ - 1) ? (PY_ - 2) : y);
        int xx = (x == 0) ? 1 : x;
        val = s[((zz - 1) * NY_ + (yy - 1)) * NX_ + (xx - 1)];
    }
    d[idx] = val;
}

// ----- fused 4-stencil (w1,w2,w3,w4) on one padded field --------------------
__global__ void k_stencil4(const float* __restrict__ src,
                           const float* __restrict__ wa, const float* __restrict__ wb,
                           const float* __restrict__ wc, const float* __restrict__ wd,
                           float* __restrict__ oa, float* __restrict__ ob,
                           float* __restrict__ oc, float* __restrict__ od) {
    int i = blockIdx.x * TPB + threadIdx.x;
    if (i >= NI_) return;
    int z = i / (NY_ * NX_); int r = i - z * NY_ * NX_; int y = r / NX_; int x = r - y * NX_;
    int p = (z + 1) * SZ_ + (y + 1) * SY_ + (x + 1);
    float n[27];
#pragma unroll
    for (int dz = 0; dz < 3; ++dz)
#pragma unroll
        for (int dy = 0; dy < 3; ++dy)
#pragma unroll
            for (int dx = 0; dx < 3; ++dx)
                n[dz * 9 + dy * 3 + dx] =
                    src[p + (dz - 1) * SZ_ + (dy - 1) * SY_ + (dx - 1)];
    float a = 0.f, b = 0.f, c = 0.f, d = 0.f;
#pragma unroll
    for (int k = 0; k < 27; ++k) {
        float nv = n[k];
        a = fmaf(__ldg(&wa[k]), nv, a);
        b = fmaf(__ldg(&wb[k]), nv, b);
        c = fmaf(__ldg(&wc[k]), nv, c);
        d = fmaf(__ldg(&wd[k]), nv, d);
    }
    oa[i] = a; ob[i] = b; oc[i] = c; od[i] = d;
}

// ----- k coefficients (all 3 fields) into padded buffers (halo = 0) ---------
__global__ void k_kcoef(const float* __restrict__ vu, const float* __restrict__ vv,
                        const float* __restrict__ vw, const float* __restrict__ k1,
                        const float* __restrict__ sg, const float* __restrict__ dtp) {
    int idx = blockIdx.x * TPB + threadIdx.x;
    if (idx >= PT_) return;
    int z = idx / SZ_; int r = idx - z * SZ_; int y = r / SY_; int x = r - y * SY_;
    if (z == 0 || z == PZ_ - 1 || y == 0 || y == PY_ - 1 || x == 0 || x == PX_ - 1) {
        g_heap[O_KUU + idx] = 0.f;
        g_heap[O_KVV + idx] = 0.f;
        g_heap[O_KWW + idx] = 0.f;
        return;
    }
    int i = ((z - 1) * NY_ + (y - 1)) * NX_ + (x - 1);
    float dt = get_dt(dtp);
    float inv = 1.f / (1.f + dt * sg[i]);
    float speed = (fabsf(vu[i]) + fabsf(vv[i]) + fabsf(vw[i])) * DX_;
    const float c = 1.f / (DX_ * DX_ * DX_);
    float lim = k1[i];
    {
        float num = 0.1f * DX_ * fabsf((1.f / 3.f) * c * speed * g_heap[O_AD2U + i]);
        float den = 0.001f + (fabsf(g_heap[O_ADXU + i]) * c + fabsf(g_heap[O_ADYU + i]) * c +
                              fabsf(g_heap[O_ADZU + i]) * c) * (1.f / 3.f);
        g_heap[O_KUU + idx] = fminf(num / den, lim) * inv;
    }
    {
        float num = 0.1f * DX_ * fabsf((1.f / 3.f) * c * speed * g_heap[O_AD2V + i]);
        float den = 0.001f + (fabsf(g_heap[O_ADXV + i]) * c + fabsf(g_heap[O_ADYV + i]) * c +
                              fabsf(g_heap[O_ADZV + i]) * c) * (1.f / 3.f);
        g_heap[O_KVV + idx] = fminf(num / den, lim) * inv;
    }
    {
        float num = 0.1f * DX_ * fabsf((1.f / 3.f) * c * speed * g_heap[O_AD2W + i]);
        float den = 0.001f + (fabsf(g_heap[O_ADXW + i]) * c + fabsf(g_heap[O_ADYW + i]) * c +
                              fabsf(g_heap[O_ADZW + i]) * c) * (1.f / 3.f);
        g_heap[O_KWW + idx] = fminf(num / den, lim) * inv;
    }
}

// ----- PG flux: 0.5*(k*AD2 + conv(f*k,w1) - f*conv(k,w1)) --------------------
__global__ void k_pgflux(const float* __restrict__ fpad, const float* __restrict__ kpad,
                         const float* __restrict__ ad2, const float* __restrict__ vel,
                         const float* __restrict__ w1p, float* __restrict__ out) {
    int i = blockIdx.x * TPB + threadIdx.x;
    if (i >= NI_) return;
    int z = i / (NY_ * NX_); int r = i - z * NY_ * NX_; int y = r / NX_; int x = r - y * NX_;
    int p = (z + 1) * SZ_ + (y + 1) * SY_ + (x + 1);
    float acc1 = 0.f, acc2 = 0.f;
#pragma unroll
    for (int dz = 0; dz < 3; ++dz)
#pragma unroll
        for (int dy = 0; dy < 3; ++dy)
#pragma unroll
            for (int dx = 0; dx < 3; ++dx) {
                int off = (dz - 1) * SZ_ + (dy - 1) * SY_ + (dx - 1);
                float wgt = __ldg(&w1p[dz * 9 + dy * 3 + dx]);
                float kv = kpad[p + off];
                acc1 = fmaf(wgt, fpad[p + off] * kv, acc1);
                acc2 = fmaf(wgt, kv, acc2);
            }
    float kc = kpad[p];
    out[i] = 0.5f * (kc * ad2[i] + acc1 - vel[i] * acc2);
}

// ----- predictor half step ---------------------------------------------------
__global__ void k_predictor(const float* __restrict__ sg, const float* __restrict__ dtp) {
    int i = blockIdx.x * TPB + threadIdx.x;
    if (i >= NI_) return;
    float dt = get_dt(dtp);
    float s = 1.f / (1.f + dt * sg[i]);
    float U = g_heap[O_U + i], V = g_heap[O_V + i], W = g_heap[O_W + i];
    g_heap[O_BU + i] = (U + 0.5f * dt * (RE_ * g_heap[O_AD2U + i] - U * g_heap[O_ADXU + i]
                          - V * g_heap[O_ADYU + i] - W * g_heap[O_ADZU + i])
                          + 0.5f * dt * g_heap[O_KX + i] - dt * g_heap[O_GPX + i]) * s;
    g_heap[O_BV + i] = (V + 0.5f * dt * (RE_ * g_heap[O_AD2V + i] - U * g_heap[O_ADXV + i]
                          - V * g_heap[O_ADYV + i] - W * g_heap[O_ADZV + i])
                          + 0.5f * dt * g_heap[O_KY + i] - dt * g_heap[O_GPY + i]) * s;
    g_heap[O_BW + i] = (W + 0.5f * dt * (RE_ * g_heap[O_AD2W + i] - U * g_heap[O_ADXW + i]
                          - V * g_heap[O_ADYW + i] - W * g_heap[O_ADZW + i])
                          + 0.5f * dt * g_heap[O_KZ + i] - dt * g_heap[O_GPZ + i]) * s;
}

// ----- corrector full step ----------------------------------------------------
__global__ void k_corrector(const float* __restrict__ sg, const float* __restrict__ dtp) {
    int i = blockIdx.x * TPB + threadIdx.x;
    if (i >= NI_) return;
    float dt = get_dt(dtp);
    float s = 1.f / (1.f + dt * sg[i]);
    float U = g_heap[O_U + i], V = g_heap[O_V + i], W = g_heap[O_W + i];
    float BU = g_heap[O_BU + i], BV = g_heap[O_BV + i], BW = g_heap[O_BW + i];
    g_heap[O_U + i] = (U + dt * (RE_ * g_heap[O_AD2U + i] - BU * g_heap[O_ADXU + i]
                         - BV * g_heap[O_ADYU + i] - BW * g_heap[O_ADZU + i]
                         + g_heap[O_KX + i]) - dt * g_heap[O_GPX + i]) * s;
    g_heap[O_V + i] = (V + dt * (RE_ * g_heap[O_AD2V + i] - BU * g_heap[O_ADXV + i]
                         - BV * g_heap[O_ADYV + i] - BW * g_heap[O_ADZV + i]
                         + g_heap[O_KY + i]) - dt * g_heap[O_GPY + i]) * s;
    g_heap[O_W + i] = (W + dt * (RE_ * g_heap[O_AD2W + i] - BU * g_heap[O_ADXW + i]
                         - BV * g_heap[O_ADYW + i] - BW * g_heap[O_ADZW + i]
                         + g_heap[O_KZ + i]) - dt * g_heap[O_GPZ + i]) * s;
}

// ----- multigrid RHS: b = -div(u)/dt ------------------------------------------
__global__ void k_divrhs(const float* __restrict__ w2, const float* __restrict__ w3,
                         const float* __restrict__ w4, const float* __restrict__ dtp) {
    int i = blockIdx.x * TPB + threadIdx.x;
    if (i >= NI_) return;
    int z = i / (NY_ * NX_); int r = i - z * NY_ * NX_; int y = r / NX_; int x = r - y * NX_;
    int p = (z + 1) * SZ_ + (y + 1) * SY_ + (x + 1);
    float a = conv27(g_heap + O_UU, p, w2);
    float b = conv27(g_heap + O_VV, p, w3);
    float c = conv27(g_heap + O_WW, p, w4);
    g_heap[O_RHS + i] = -(a + b + c) / get_dt(dtp);
}

// ----- residual level 0 ---------------------------------------------------------
__global__ void k_resid0(const float* __restrict__ wA) {
    int i = blockIdx.x * TPB + threadIdx.x;
    if (i >= NI_) return;
    int z = i / (NY_ * NX_); int r = i - z * NY_ * NX_; int y = r / NX_; int x = r - y * NX_;
    int p = (z + 1) * SZ_ + (y + 1) * SY_ + (x + 1);
    g_heap[O_R0 + i] = conv27(g_heap + O_PPb, p, wA) - g_heap[O_RHS + i];
}

// ----- restriction (2x2x2 weighted avg, stride 2) -------------------------------
__global__ void k_restrict(const float* __restrict__ fine, float* __restrict__ coarse,
                           int cz, int cy, int cx, const float* __restrict__ wr) {
    int n = cz * cy * cx;
    int i = blockIdx.x * TPB + threadIdx.x;
    if (i >= n) return;
    int z = i / (cy * cx); int r = i - z * cy * cx; int y = r / cx; int x = r - y * cx;
    int fsy = 2 * cx;
    int fsz = fsy * 2 * cy;
    int base = (2 * z) * fsz + (2 * y) * fsy + 2 * x;
    float acc = 0.f;
#pragma unroll
    for (int jz = 0; jz < 2; ++jz)
#pragma unroll
        for (int jy = 0; jy < 2; ++jy)
#pragma unroll
            for (int jx = 0; jx < 2; ++jx)
                acc = fmaf(__ldg(&wr[jz * 4 + jy * 2 + jx]),
                           fine[base + jz * fsz + jy * fsy + jx], acc);
    coarse[i] = acc;
}

// ----- fused Jacobi smooth + prolongation ---------------------------------------
__global__ void k_smooth_prol(const float* __restrict__ wc, const float* __restrict__ rr,
                              float* __restrict__ wn, int dzs, int dys, int dxs,
                              const float* __restrict__ wA) {
    int n = dzs * dys * dxs;
    int i = blockIdx.x * TPB + threadIdx.x;
    if (i >= n) return;
    int z = i / (dys * dxs); int r = i - z * dys * dxs; int y = r / dxs; int x = r - y * dxs;
    float diag = __ldg(&wA[13]);
    float acc = 0.f;
#pragma unroll
    for (int dz = -1; dz <= 1; ++dz)
#pragma unroll
        for (int dy = -1; dy <= 1; ++dy)
#pragma unroll
            for (int dx = -1; dx <= 1; ++dx) {
                int zz = z + dz, yy = y + dy, xx = x + dx;
                float v = 0.f;
                if (zz >= 0 && zz < dzs && yy >= 0 && yy < dys && xx >= 0 && xx < dxs)
                    v = wc[(zz * dys + yy) * dxs + xx];
                acc = fmaf(__ldg(&wA[(dz + 1) * 9 + (dy + 1) * 3 + (dx + 1)]), v, acc);
            }
    float val = wc[i] - acc / diag + rr[i] / diag;
    int fsy = 2 * dxs;
    int fsz = fsy * 2 * dys;
    int fb = (2 * z) * fsz + (2 * y) * fsy + 2 * x;
    wn[fb] = val;             wn[fb + 1] = val;
    wn[fb + fsy] = val;       wn[fb + fsy + 1] = val;
    wn[fb + fsz] = val;       wn[fb + fsz + 1] = val;
    wn[fb + fsz + fsy] = val; wn[fb + fsz + fsy + 1] = val;
}

// ----- p -= w0 -------------------------------------------------------------------
__global__ void k_psub() {
    int i = blockIdx.x * TPB + threadIdx.x;
    if (i >= NI_) return;
    g_heap[O_P + i] -= g_heap[O_MW0 + i];
}

// ----- p = p - conv(pp,wA)/diag + rhs/diag ----------------------------------------
__global__ void k_pupdate(const float* __restrict__ wA) {
    int i = blockIdx.x * TPB + threadIdx.x;
    if (i >= NI_) return;
    int z = i / (NY_ * NX_); int r = i - z * NY_ * NX_; int y = r / NX_; int x = r - y * NX_;
    int p = (z + 1) * SZ_ + (y + 1) * SY_ + (x + 1);
    float diag = __ldg(&wA[13]);
    float cv = conv27(g_heap + O_PPb, p, wA);
    g_heap[O_P + i] = g_heap[O_P + i] - cv / diag + g_heap[O_RHS + i] / diag;
}

// ----- final: u -= grad(p)*dt, solid_body, write outputs --------------------------
__global__ void k_final(const float* __restrict__ w2, const float* __restrict__ w3,
                        const float* __restrict__ w4, const float* __restrict__ sg,
                        const float* __restrict__ dtp, float* __restrict__ out) {
    int i = blockIdx.x * TPB + threadIdx.x;
    if (i >= NI_) return;
    int z = i / (NY_ * NX_); int r = i - z * NY_ * NX_; int y = r / NX_; int x = r - y * NX_;
    int p = (z + 1) * SZ_ + (y + 1) * SY_ + (x + 1);
    float n[27];
#pragma unroll
    for (int dz = 0; dz < 3; ++dz)
#pragma unroll
        for (int dy = 0; dy < 3; ++dy)
#pragma unroll
            for (int dx = 0; dx < 3; ++dx)
                n[dz * 9 + dy * 3 + dx] =
                    g_heap[O_PPb + p + (dz - 1) * SZ_ + (dy - 1) * SY_ + (dx - 1)];
    float gx = 0.f, gy = 0.f, gz = 0.f;
#pragma unroll
    for (int k = 0; k < 27; ++k) {
        float nv = n[k];
        gx = fmaf(__ldg(&w2[k]), nv, gx);
        gy = fmaf(__ldg(&w3[k]), nv, gy);
        gz = fmaf(__ldg(&w4[k]), nv, gz);
    }
    float dt = get_dt(dtp);
    float s = 1.f / (1.f + dt * sg[i]);
    out[i] = (g_heap[O_U + i] - dt * gx) * s;
    out[(long long)NI_ + i] = (g_heap[O_V + i] - dt * gy) * s;
    out[2LL * NI_ + i] = (g_heap[O_W + i] - dt * gz) * s;
    out[3LL * NI_ + i] = g_heap[O_P + i];
    out[4LL * NI_ + i] = g_heap[O_MW0 + i];
}

// ---------------------------------------------------------------------------
extern "C" void kernel_launch(void* const* d_in, const int* in_sizes, int n_in,
                              void* d_out, int out_size) {
    const float* in_u = (const float*)d_in[0];
    const float* in_v = (const float*)d_in[2];
    const float* in_w = (const float*)d_in[4];
    const float* in_p = (const float*)d_in[6];
    const float* k1   = (const float*)d_in[11];
    const float* sg   = (const float*)d_in[15];
    const float* wA   = (const float*)d_in[16];
    const float* w1   = (const float*)d_in[17];
    const float* w2   = (const float*)d_in[18];
    const float* w3   = (const float*)d_in[19];
    const float* w4   = (const float*)d_in[20];
    const float* wres = (const float*)d_in[21];

    float* H = nullptr;
    cudaGetSymbolAddress((void**)&H, g_heap);

    const float* dtp;
    if (n_in > 22) {
        dtp = (const float*)d_in[22];
    } else {
        float* fb = nullptr;
        cudaGetSymbolAddress((void**)&fb, g_dt_fb);
        dtp = fb;
    }

    float* out = (float*)d_out;
    const int GI = (NI_ + TPB - 1) / TPB;
    const int GP = (PT_ + TPB - 1) / TPB;

    // stage A: solid body, BCs, stencils, PG, predictor
    k_solid<<<GI, TPB>>>(in_u, in_v, in_w, sg, dtp);
    k_bc_u<<<GP, TPB>>>(H + O_U, H + O_UU);
    k_bc_v<<<GP, TPB>>>(H + O_V, H + O_VV);
    k_bc_w<<<GP, TPB>>>(H + O_W, H + O_WW);
    k_bc_p<<<GP, TPB>>>(in_p, H + O_PPb);
    k_stencil4<<<GI, TPB>>>(H + O_UU, w1, w2, w3, w4, H + O_AD2U, H + O_ADXU, H + O_ADYU, H + O_ADZU);
    k_stencil4<<<GI, TPB>>>(H + O_VV, w1, w2, w3, w4, H + O_AD2V, H + O_ADXV, H + O_ADYV, H + O_ADZV);
    k_stencil4<<<GI, TPB>>>(H + O_WW, w1, w2, w3, w4, H + O_AD2W, H + O_ADXW, H + O_ADYW, H + O_ADZW);
    k_stencil4<<<GI, TPB>>>(H + O_PPb, w1, w2, w3, w4, H + O_SCR, H + O_GPX, H + O_GPY, H + O_GPZ);
    k_kcoef<<<GP, TPB>>>(H + O_U, H + O_V, H + O_W, k1, sg, dtp);
    k_pgflux<<<GI, TPB>>>(H + O_UU, H + O_KUU, H + O_AD2U, H + O_U, w1, H + O_KX);
    k_pgflux<<<GI, TPB>>>(H + O_VV, H + O_KVV, H + O_AD2V, H + O_V, w1, H + O_KY);
    k_pgflux<<<GI, TPB>>>(H + O_WW, H + O_KWW, H + O_AD2W, H + O_W, w1, H + O_KZ);
    k_predictor<<<GI, TPB>>>(sg, dtp);

    // stage B: BCs on predictor, stencils, PG, corrector
    k_bc_u<<<GP, TPB>>>(H + O_BU, H + O_UU);
    k_bc_v<<<GP, TPB>>>(H + O_BV, H + O_VV);
    k_bc_w<<<GP, TPB>>>(H + O_BW, H + O_WW);
    k_stencil4<<<GI, TPB>>>(H + O_UU, w1, w2, w3, w4, H + O_AD2U, H + O_ADXU, H + O_ADYU, H + O_ADZU);
    k_stencil4<<<GI, TPB>>>(H + O_VV, w1, w2, w3, w4, H + O_AD2V, H + O_ADXV, H + O_ADYV, H + O_ADZV);
    k_stencil4<<<GI, TPB>>>(H + O_WW, w1, w2, w3, w4, H + O_AD2W, H + O_ADXW, H + O_ADYW, H + O_ADZW);
    k_kcoef<<<GP, TPB>>>(H + O_BU, H + O_BV, H + O_BW, k1, sg, dtp);
    k_pgflux<<<GI, TPB>>>(H + O_UU, H + O_KUU, H + O_AD2U, H + O_BU, w1, H + O_KX);
    k_pgflux<<<GI, TPB>>>(H + O_VV, H + O_KVV, H + O_AD2V, H + O_BV, w1, H + O_KY);
    k_pgflux<<<GI, TPB>>>(H + O_WW, H + O_KWW, H + O_AD2W, H + O_BW, w1, H + O_KZ);
    k_corrector<<<GI, TPB>>>(sg, dtp);

    // final BCs + multigrid pressure solve
    k_bc_u<<<GP, TPB>>>(H + O_U, H + O_UU);
    k_bc_v<<<GP, TPB>>>(H + O_V, H + O_VV);
    k_bc_w<<<GP, TPB>>>(H + O_W, H + O_WW);
    k_divrhs<<<GI, TPB>>>(w2, w3, w4, dtp);
    cudaMemcpyAsync(H + O_P, in_p, (size_t)NI_ * sizeof(float), cudaMemcpyDeviceToDevice, 0);

    for (int it = 0; it < 2; ++it) {   // ITERATION = 2 (fixed by problem)
        k_bc_p<<<GP, TPB>>>(H + O_P, H + O_PPb);
        k_resid0<<<GI, TPB>>>(wA);
        k_restrict<<<(L1_ + TPB - 1) / TPB, TPB>>>(H + O_R0, H + O_R1, 32, 128, 128, wres);
        k_restrict<<<(L2_ + TPB - 1) / TPB, TPB>>>(H + O_R1, H + O_R2, 16, 64, 64, wres);
        k_restrict<<<(L3_ + TPB - 1) / TPB, TPB>>>(H + O_R2, H + O_R3, 8, 32, 32, wres);
        k_restrict<<<(L4_ + TPB - 1) / TPB, TPB>>>(H + O_R3, H + O_R4, 4, 16, 16, wres);
        k_restrict<<<1, TPB>>>(H + O_R4, H + O_R5, 2, 8, 8, wres);
        cudaMemsetAsync(H + O_MW5, 0, L5_ * sizeof(float), 0);
        k_smooth_prol<<<1, TPB>>>(H + O_MW5, H + O_R5, H + O_MW4, 2, 8, 8, wA);
        k_smooth_prol<<<(L4_ + TPB - 1) / TPB, TPB>>>(H + O_MW4, H + O_R4, H + O_MW3, 4, 16, 16, wA);
        k_smooth_prol<<<(L3_ + TPB - 1) / TPB, TPB>>>(H + O_MW3, H + O_R3, H + O_MW2, 8, 32, 32, wA);
        k_smooth_prol<<<(L2_ + TPB - 1) / TPB, TPB>>>(H + O_MW2, H + O_R2, H + O_MW1, 16, 64, 64, wA);
        k_smooth_prol<<<(L1_ + TPB - 1) / TPB, TPB>>>(H + O_MW1, H + O_R1, H + O_MW0, 32, 128, 128, wA);
        k_psub<<<GI, TPB>>>();
        k_bc_p<<<GP, TPB>>>(H + O_P, H + O_PPb);
        k_pupdate<<<GI, TPB>>>(wA);
    }

    // velocity correction + outputs
    k_bc_p<<<GP, TPB>>>(H + O_P, H + O_PPb);
    k_final<<<GI, TPB>>>(w2, w3, w4, sg, dtp, out);
    cudaMemcpyAsync(out + 5LL * NI_, H + O_R5, L5_ * sizeof(float),
                    cudaMemcpyDeviceToDevice, 0);
}